// round 13
// baseline (speedup 1.0000x reference)
#include <cuda_runtime.h>
#include <cuda_bf16.h>
#include <math.h>
#include <cstdint>

// ---------------- problem constants ----------------
#define BATCH 2048
#define TT 30
#define ACT 6
#define STOCH 64
#define DETER 1024
#define HIDDEN 1024
#define OUTW (2*STOCH + DETER)   // 1152
#define KIN (STOCH + ACT)        // 70
#define LN_EPS 1e-5f

// ---------------- device state buffers ----------------
__device__ __align__(16) __nv_bfloat16 g_ahi[(size_t)BATCH * 2048];
__device__ __align__(16) __nv_bfloat16 g_alo[(size_t)BATCH * 2048];
__device__ __align__(16) float g_deter[(size_t)BATCH * DETER];
__device__ __align__(16) float g_stoch[(size_t)BATCH * STOCH];
__device__ __align__(16) float g_parts[(size_t)BATCH * 3072];
__device__ __align__(16) float g_e1raw[(size_t)BATCH * 1024];
__device__ __align__(16) __nv_bfloat16 g_wgru_hi[(size_t)3072 * 2048];
__device__ __align__(16) __nv_bfloat16 g_wgru_lo[(size_t)3072 * 2048];
__device__ __align__(16) __nv_bfloat16 g_we1_hi[(size_t)1024 * 1024];
__device__ __align__(16) __nv_bfloat16 g_we1_lo[(size_t)1024 * 1024];

// ---------------- generic helpers ----------------
__device__ __forceinline__ void blockReduce2(float& s, float& ss, float* red) {
    __syncthreads();
#pragma unroll
    for (int o = 16; o > 0; o >>= 1) {
        s  += __shfl_down_sync(0xffffffffu, s, o);
        ss += __shfl_down_sync(0xffffffffu, ss, o);
    }
    int warp = threadIdx.x >> 5, lane = threadIdx.x & 31;
    if (lane == 0) { red[warp] = s; red[8 + warp] = ss; }
    __syncthreads();
    if (threadIdx.x < 32) {
        float a = lane < 8 ? red[lane] : 0.f;
        float c = lane < 8 ? red[8 + lane] : 0.f;
#pragma unroll
        for (int o = 4; o > 0; o >>= 1) {
            a += __shfl_down_sync(0xffffffffu, a, o);
            c += __shfl_down_sync(0xffffffffu, c, o);
        }
        if (lane == 0) { red[0] = a; red[1] = c; }
    }
    __syncthreads();
    s = red[0]; ss = red[1];
}

__device__ __forceinline__ float elu1(float v) { return v > 0.f ? v : expm1f(v); }
__device__ __forceinline__ float sigmoidf(float v) { return 1.f / (1.f + expf(-v)); }

__device__ __forceinline__ uint32_t bpack(float a, float b) {
    __nv_bfloat162 t = __floats2bfloat162_rn(a, b);
    return *reinterpret_cast<uint32_t*>(&t);
}

__device__ __forceinline__ void split_store4(const float* v, __nv_bfloat16* hip, __nv_bfloat16* lop) {
    float hf[4], lf[4];
#pragma unroll
    for (int q = 0; q < 4; q++) {
        hf[q] = __bfloat162float(__float2bfloat16(v[q]));
        lf[q] = v[q] - hf[q];
    }
    *reinterpret_cast<uint2*>(hip) = make_uint2(bpack(hf[0], hf[1]), bpack(hf[2], hf[3]));
    *reinterpret_cast<uint2*>(lop) = make_uint2(bpack(lf[0], lf[1]), bpack(lf[2], lf[3]));
}

// ---------------- async-copy + ldmatrix + mma helpers ----------------
__device__ __forceinline__ uint32_t smem_u32(const void* p) {
    return (uint32_t)__cvta_generic_to_shared(p);
}
__device__ __forceinline__ void cpa16(uint32_t dst, const void* src) {
    asm volatile("cp.async.cg.shared.global [%0], [%1], 16;\n" :: "r"(dst), "l"(src));
}
__device__ __forceinline__ void cpa_commit() { asm volatile("cp.async.commit_group;\n" ::: "memory"); }
__device__ __forceinline__ void cpa_wait1()  { asm volatile("cp.async.wait_group 1;\n" ::: "memory"); }
__device__ __forceinline__ void cpa_wait0()  { asm volatile("cp.async.wait_group 0;\n" ::: "memory"); }

#define SWZ64(off) ((off) ^ (((off) >> 3) & 0x30))

__device__ __forceinline__ void ldsm_x4(uint32_t* r, uint32_t addr) {
    asm volatile("ldmatrix.sync.aligned.m8n8.x4.shared.b16 {%0,%1,%2,%3}, [%4];"
                 : "=r"(r[0]), "=r"(r[1]), "=r"(r[2]), "=r"(r[3]) : "r"(addr));
}
__device__ __forceinline__ void mma16816(float* c, const uint32_t* a, uint32_t b0, uint32_t b1) {
    asm volatile(
        "mma.sync.aligned.m16n8k16.row.col.f32.bf16.bf16.f32 "
        "{%0,%1,%2,%3}, {%4,%5,%6,%7}, {%8,%9}, {%0,%1,%2,%3};"
        : "+f"(c[0]), "+f"(c[1]), "+f"(c[2]), "+f"(c[3])
        : "r"(a[0]), "r"(a[1]), "r"(a[2]), "r"(a[3]), "r"(b0), "r"(b1));
}

// ---------------- init ----------------
__global__ void init_kernel() {
    int idx = blockIdx.x * blockDim.x + threadIdx.x;
    if (idx < BATCH * DETER) {
        int r = idx >> 10, c = idx & 1023;
        g_deter[idx] = 0.f;
        g_ahi[(size_t)r * 2048 + 1024 + c] = __float2bfloat16(0.f);
        g_alo[(size_t)r * 2048 + 1024 + c] = __float2bfloat16(0.f);
    }
    if (idx < BATCH * STOCH) g_stoch[idx] = 0.f;
}

// ---------------- weight prep ----------------
__global__ __launch_bounds__(256) void wprep_kernel(
    const float* __restrict__ W, __nv_bfloat16* __restrict__ Whi,
    __nv_bfloat16* __restrict__ Wlo, int K, int N)
{
    __shared__ float s[32][33];
    int tx = threadIdx.x & 31, ty = threadIdx.x >> 5;
    int n0 = blockIdx.x * 32, k0 = blockIdx.y * 32;
#pragma unroll
    for (int j = 0; j < 4; j++)
        s[ty + j * 8][tx] = W[(size_t)(k0 + ty + j * 8) * N + n0 + tx];
    __syncthreads();
#pragma unroll
    for (int j = 0; j < 4; j++) {
        int n = n0 + ty + j * 8;
        int k = k0 + tx;
        float v = s[tx][ty + j * 8];
        __nv_bfloat16 h = __float2bfloat16(v);
        Whi[(size_t)n * K + k] = h;
        Wlo[(size_t)n * K + k] = __float2bfloat16(v - __bfloat162float(h));
    }
}

// ---------------- K1: img layer (16 rows/block, register-resident, no vals smem) ----------------
__global__ __launch_bounds__(256) void img_kernel(
    const float* __restrict__ action, const float* __restrict__ W,
    const float* __restrict__ bvec, const float* __restrict__ gvec,
    const float* __restrict__ beta, int t)
{
    __shared__ float xin[16][72];
    __shared__ float red[64];
    int tid = threadIdx.x;
    int b0 = blockIdx.x * 16;

    for (int e = tid; e < 16 * KIN; e += 256) {
        int r = e / KIN, k = e % KIN;
        xin[r][k] = (k < STOCH) ? g_stoch[(size_t)(b0 + r) * STOCH + k]
                                : action[(size_t)(b0 + r) * (TT * ACT) + t * ACT + (k - STOCH)];
    }
    __syncthreads();

    int j0 = tid * 4;
    float acc[16][4];
    {
        float4 bv = *reinterpret_cast<const float4*>(&bvec[j0]);
#pragma unroll
        for (int r = 0; r < 16; r++) {
            acc[r][0] = bv.x; acc[r][1] = bv.y; acc[r][2] = bv.z; acc[r][3] = bv.w;
        }
        for (int k = 0; k < KIN; k++) {
            float4 w = *reinterpret_cast<const float4*>(&W[k * 1024 + j0]);
#pragma unroll
            for (int r = 0; r < 16; r++) {
                float xv = xin[r][k];
                acc[r][0] = fmaf(xv, w.x, acc[r][0]);
                acc[r][1] = fmaf(xv, w.y, acc[r][1]);
                acc[r][2] = fmaf(xv, w.z, acc[r][2]);
                acc[r][3] = fmaf(xv, w.w, acc[r][3]);
            }
        }
    }

    float4 g4 = *reinterpret_cast<const float4*>(&gvec[j0]);
    float4 b4 = *reinterpret_cast<const float4*>(&beta[j0]);
    float gv[4] = {g4.x, g4.y, g4.z, g4.w};
    float bb[4] = {b4.x, b4.y, b4.z, b4.w};

    for (int r = 0; r < 16; r++) {
        float s  = acc[r][0] + acc[r][1] + acc[r][2] + acc[r][3];
        float ss = acc[r][0] * acc[r][0] + acc[r][1] * acc[r][1]
                 + acc[r][2] * acc[r][2] + acc[r][3] * acc[r][3];
        blockReduce2(s, ss, red);
        float mean = s * (1.f / 1024.f);
        float rstd = rsqrtf(ss * (1.f / 1024.f) - mean * mean + LN_EPS);
        float x[4];
#pragma unroll
        for (int q = 0; q < 4; q++)
            x[q] = elu1((acc[r][q] - mean) * rstd * gv[q] + bb[q]);
        size_t o = (size_t)(b0 + r) * 2048 + j0;
        split_store4(x, &g_ahi[o], &g_alo[o]);
    }
}

// ---------------- K2: bf16x3 GEMM, per-slab 3-product, templated warp-N ----------------
template<int WN>
__global__ void __launch_bounds__(256, 2) mma_gemm_t(int mode)
{
    constexpr int TN = 4 * WN;
    constexpr int NT = WN / 8;
    constexpr int NF = WN / 16;
    constexpr uint32_t B_BYTES = (uint32_t)TN * 64u;
    constexpr uint32_t STG = 16384u + 2u * B_BYTES;
    constexpr uint32_t T_AHI = 0u, T_ALO = 8192u, T_BHI = 16384u, T_BLO = 16384u + B_BYTES;

    extern __shared__ char smraw[];
    uint32_t base = smem_u32(smraw);

    const __nv_bfloat16 *Ahi, *Alo, *Bhi, *Blo;
    float* C;
    int lda, ldb, ldc, Kseg;
    if (mode == 0) {
        Ahi = g_ahi; Alo = g_alo; lda = 2048; Kseg = 2048;
        Bhi = g_wgru_hi; Blo = g_wgru_lo; ldb = 2048;
        C = g_parts; ldc = 3072;
    } else {
        Ahi = g_ahi + 1024; Alo = g_alo + 1024; lda = 2048; Kseg = 1024;
        Bhi = g_we1_hi; Blo = g_we1_lo; ldb = 1024;
        C = g_e1raw; ldc = 1024;
    }
    const int SLABS = Kseg >> 5;

    int tid = threadIdx.x;
    int wid = tid >> 5, lane = tid & 31;
    int row0 = blockIdx.y * 128;
    int col0 = blockIdx.x * TN;

    float acc[4][NT][4];
#pragma unroll
    for (int i = 0; i < 4; i++)
#pragma unroll
        for (int j = 0; j < NT; j++)
#pragma unroll
            for (int q = 0; q < 4; q++) acc[i][j][q] = 0.f;

    auto load_slab = [&](int s, int buf) {
        int k0 = s << 5;
        uint32_t st = base + (uint32_t)buf * STG;
#pragma unroll
        for (int i = 0; i < 2; i++) {
            int e = tid + i * 256;
            int r = e >> 2, c = e & 3;
            uint32_t so = SWZ64(r * 64 + c * 16);
            cpa16(st + T_AHI + so, Ahi + (size_t)(row0 + r) * lda + k0 + c * 8);
            cpa16(st + T_ALO + so, Alo + (size_t)(row0 + r) * lda + k0 + c * 8);
        }
#pragma unroll
        for (int i = 0; i < TN / 64; i++) {
            int e = tid + i * 256;
            int r = e >> 2, c = e & 3;
            uint32_t so = SWZ64(r * 64 + c * 16);
            cpa16(st + T_BHI + so, Bhi + (size_t)(col0 + r) * ldb + k0 + c * 8);
            cpa16(st + T_BLO + so, Blo + (size_t)(col0 + r) * ldb + k0 + c * 8);
        }
        cpa_commit();
    };

    int m0w = (wid & 1) * 64;
    int n0w = (wid >> 1) * WN;
    int grp = lane >> 3, rin = lane & 7;

    load_slab(0, 0);
    load_slab(1, 1);

    for (int s = 0; s < SLABS; s++) {
        int buf = s % 3;
        if (s + 1 < SLABS) cpa_wait1();
        else               cpa_wait0();
        __syncthreads();
        if (s + 2 < SLABS) load_slab(s + 2, (s + 2) % 3);

        uint32_t st = base + (uint32_t)buf * STG;
#pragma unroll
        for (int kk = 0; kk < 2; kk++) {
            int a_row = rin + (grp & 1) * 8;
            int a_ch  = kk * 2 + (grp >> 1);
            int b_row = rin + (grp >> 1) * 8;
            int b_ch  = kk * 2 + (grp & 1);

            uint32_t bh[NF][4], bl[NF][4];
#pragma unroll
            for (int nt2 = 0; nt2 < NF; nt2++) {
                uint32_t bo = SWZ64((n0w + nt2 * 16 + b_row) * 64 + b_ch * 16);
                ldsm_x4(bh[nt2], st + T_BHI + bo);
                ldsm_x4(bl[nt2], st + T_BLO + bo);
            }
#pragma unroll
            for (int mt = 0; mt < 4; mt++) {
                uint32_t ao = SWZ64((m0w + mt * 16 + a_row) * 64 + a_ch * 16);
                uint32_t ah[4], al[4];
                ldsm_x4(ah, st + T_AHI + ao);
                ldsm_x4(al, st + T_ALO + ao);
#pragma unroll
                for (int nt = 0; nt < NT; nt++) {
                    uint32_t h0 = bh[nt >> 1][(nt & 1) * 2], h1 = bh[nt >> 1][(nt & 1) * 2 + 1];
                    uint32_t l0 = bl[nt >> 1][(nt & 1) * 2], l1 = bl[nt >> 1][(nt & 1) * 2 + 1];
                    mma16816(acc[mt][nt], ah, h0, h1);   // hi*hi
                    mma16816(acc[mt][nt], al, h0, h1);   // lo*hi
                    mma16816(acc[mt][nt], ah, l0, l1);   // hi*lo
                }
            }
        }
    }

#pragma unroll
    for (int mt = 0; mt < 4; mt++) {
        int r0 = row0 + m0w + mt * 16 + (lane >> 2);
#pragma unroll
        for (int nt = 0; nt < NT; nt++) {
            int cc = col0 + n0w + nt * 8 + (lane & 3) * 2;
            *reinterpret_cast<float2*>(&C[(size_t)r0 * ldc + cc]) =
                make_float2(acc[mt][nt][0], acc[mt][nt][1]);
            *reinterpret_cast<float2*>(&C[(size_t)(r0 + 8) * ldc + cc]) =
                make_float2(acc[mt][nt][2], acc[mt][nt][3]);
        }
    }
}

// ---------------- K3: GRU gates (register-resident, float4) ----------------
__global__ __launch_bounds__(256) void gru_kernel(
    const float* __restrict__ bgru, const float* __restrict__ ggru,
    const float* __restrict__ betag, float* __restrict__ out, int t)
{
    __shared__ float red[64];
    int b = blockIdx.x, tid = threadIdx.x;
    const float4* row4 = reinterpret_cast<const float4*>(g_parts + (size_t)b * 3072);
    const float4* bg4  = reinterpret_cast<const float4*>(bgru);

    float4 loc[3];
    float s = 0.f, ss = 0.f;
#pragma unroll
    for (int jj = 0; jj < 3; jj++) {
        float4 x = row4[tid + jj * 256];
        float4 bb = bg4[tid + jj * 256];
        x.x += bb.x; x.y += bb.y; x.z += bb.z; x.w += bb.w;
        loc[jj] = x;
        s += x.x + x.y + x.z + x.w;
        ss += x.x * x.x + x.y * x.y + x.z * x.z + x.w * x.w;
    }
    blockReduce2(s, ss, red);
    float mean = s * (1.f / 3072.f);
    float rstd = rsqrtf(ss * (1.f / 3072.f) - mean * mean + LN_EPS);

    const float4* gg4 = reinterpret_cast<const float4*>(ggru);
    const float4* bt4 = reinterpret_cast<const float4*>(betag);
    float V[3][4];
#pragma unroll
    for (int jj = 0; jj < 3; jj++) {
        float4 g = gg4[tid + jj * 256];
        float4 be = bt4[tid + jj * 256];
        V[jj][0] = (loc[jj].x - mean) * rstd * g.x + be.x;
        V[jj][1] = (loc[jj].y - mean) * rstd * g.y + be.y;
        V[jj][2] = (loc[jj].z - mean) * rstd * g.z + be.z;
        V[jj][3] = (loc[jj].w - mean) * rstd * g.w + be.w;
    }

    float4 dp = *reinterpret_cast<const float4*>(&g_deter[(size_t)b * 1024 + tid * 4]);
    float dpv[4] = {dp.x, dp.y, dp.z, dp.w};
    float dn[4];
#pragma unroll
    for (int q = 0; q < 4; q++) {
        float reset  = sigmoidf(V[0][q]);
        float cand   = tanhf(reset * V[1][q]);
        float update = sigmoidf(V[2][q] - 1.f);
        dn[q] = update * cand + (1.f - update) * dpv[q];
    }
    *reinterpret_cast<float4*>(&g_deter[(size_t)b * 1024 + tid * 4]) =
        make_float4(dn[0], dn[1], dn[2], dn[3]);
    *reinterpret_cast<float4*>(&out[(size_t)b * (TT * OUTW) + (size_t)t * OUTW + 128 + tid * 4]) =
        make_float4(dn[0], dn[1], dn[2], dn[3]);
    size_t o = (size_t)b * 2048 + 1024 + tid * 4;
    split_store4(dn, &g_ahi[o], &g_alo[o]);
}

// ---------------- K6: fused e1-LN/ELU + e2 GEMM + stats (8 rows/block) ----------------
__global__ __launch_bounds__(256) void e2_fused_kernel(
    const float* __restrict__ be1, const float* __restrict__ ge1,
    const float* __restrict__ betae1,
    const float* __restrict__ W, const float* __restrict__ bias,
    float* __restrict__ out, int t)
{
    __shared__ float hs[8][33];
    __shared__ float ws[32][128];
    __shared__ float smean[8], srstd[8];
    int tid = threadIdx.x;
    int r0 = blockIdx.x * 8;
    int w = tid >> 5, lane = tid & 31;

    {
        const float4* row4 = reinterpret_cast<const float4*>(g_e1raw + (size_t)(r0 + w) * 1024);
        const float4* b4 = reinterpret_cast<const float4*>(be1);
        float s = 0.f, ss = 0.f;
#pragma unroll
        for (int i = 0; i < 8; i++) {
            float4 x = row4[lane + i * 32];
            float4 bb = b4[lane + i * 32];
            x.x += bb.x; x.y += bb.y; x.z += bb.z; x.w += bb.w;
            s += x.x + x.y + x.z + x.w;
            ss += x.x * x.x + x.y * x.y + x.z * x.z + x.w * x.w;
        }
#pragma unroll
        for (int o = 16; o > 0; o >>= 1) {
            s  += __shfl_down_sync(0xffffffffu, s, o);
            ss += __shfl_down_sync(0xffffffffu, ss, o);
        }
        if (lane == 0) {
            float mean = s * (1.f / 1024.f);
            smean[w] = mean;
            srstd[w] = rsqrtf(ss * (1.f / 1024.f) - mean * mean + LN_EPS);
        }
    }
    __syncthreads();

    int col = tid & 127, rl = tid >> 7;
    float acc[4];
#pragma unroll
    for (int q = 0; q < 4; q++) acc[q] = 0.f;

    for (int k0 = 0; k0 < 1024; k0 += 32) {
        if (tid < 64) {
            int rr = tid >> 3, k4 = (tid & 7) * 4;
            int c = k0 + k4;
            float4 v = *reinterpret_cast<const float4*>(&g_e1raw[(size_t)(r0 + rr) * 1024 + c]);
            float4 bb = *reinterpret_cast<const float4*>(&be1[c]);
            float4 g  = *reinterpret_cast<const float4*>(&ge1[c]);
            float4 be = *reinterpret_cast<const float4*>(&betae1[c]);
            float mean = smean[rr], rstd = srstd[rr];
            hs[rr][k4]     = elu1(((v.x + bb.x) - mean) * rstd * g.x + be.x);
            hs[rr][k4 + 1] = elu1(((v.y + bb.y) - mean) * rstd * g.y + be.y);
            hs[rr][k4 + 2] = elu1(((v.z + bb.z) - mean) * rstd * g.z + be.z);
            hs[rr][k4 + 3] = elu1(((v.w + bb.w) - mean) * rstd * g.w + be.w);
        }
#pragma unroll
        for (int i = 0; i < 4; i++) {
            int idx = tid + i * 256;
            int kk = idx >> 5, c4 = (idx & 31) * 4;
            float4 v = *reinterpret_cast<const float4*>(&W[(size_t)(k0 + kk) * 128 + c4]);
            ws[kk][c4] = v.x; ws[kk][c4 + 1] = v.y; ws[kk][c4 + 2] = v.z; ws[kk][c4 + 3] = v.w;
        }
        __syncthreads();
#pragma unroll
        for (int kk = 0; kk < 32; kk++) {
            float wv = ws[kk][col];
#pragma unroll
            for (int q = 0; q < 4; q++)
                acc[q] = fmaf(hs[rl + 2 * q][kk], wv, acc[q]);
        }
        __syncthreads();
    }

    float bv = bias[col];
#pragma unroll
    for (int q = 0; q < 4; q++) {
        int r = r0 + rl + 2 * q;
        float sv = acc[q] + bv;
        if (col < 64) {
            g_stoch[(size_t)r * STOCH + col] = sv;
            out[(size_t)r * (TT * OUTW) + (size_t)t * OUTW + col] = sv;
        } else {
            float sp = fmaxf(sv, 0.f) + log1pf(expf(-fabsf(sv)));
            out[(size_t)r * (TT * OUTW) + (size_t)t * OUTW + col] = sp + 0.1f;
        }
    }
}

// ---------------- launcher ----------------
#define MMA_SMEM_32 98304    // 3 x (16384 + 2*8192)
#define MMA_SMEM_16 73728    // 3 x (16384 + 2*4096)

extern "C" void kernel_launch(void* const* d_in, const int* in_sizes, int n_in,
                              void* d_out, int out_size)
{
    const float* action   = (const float*)d_in[0];
    const float* W_img    = (const float*)d_in[1];
    const float* b_img    = (const float*)d_in[2];
    const float* g_img    = (const float*)d_in[3];
    const float* beta_img = (const float*)d_in[4];
    const float* W_gru    = (const float*)d_in[5];
    const float* b_gru    = (const float*)d_in[6];
    const float* g_gru    = (const float*)d_in[7];
    const float* beta_gru = (const float*)d_in[8];
    const float* W_e1     = (const float*)d_in[9];    // [5,1024,1024] -> slice 0
    const float* b_e1     = (const float*)d_in[10];
    const float* g_e1     = (const float*)d_in[11];
    const float* beta_e1  = (const float*)d_in[12];
    const float* W_e2     = (const float*)d_in[13];   // [5,1024,128] -> slice 0
    const float* b_e2     = (const float*)d_in[14];
    float* out = (float*)d_out;

    cudaFuncSetAttribute(mma_gemm_t<32>, cudaFuncAttributeMaxDynamicSharedMemorySize, MMA_SMEM_32);
    cudaFuncSetAttribute(mma_gemm_t<16>, cudaFuncAttributeMaxDynamicSharedMemorySize, MMA_SMEM_16);

    init_kernel<<<(BATCH * DETER + 255) / 256, 256>>>();

    __nv_bfloat16 *wgh, *wgl, *weh, *wel;
    cudaGetSymbolAddress((void**)&wgh, g_wgru_hi);
    cudaGetSymbolAddress((void**)&wgl, g_wgru_lo);
    cudaGetSymbolAddress((void**)&weh, g_we1_hi);
    cudaGetSymbolAddress((void**)&wel, g_we1_lo);
    wprep_kernel<<<dim3(3072 / 32, 2048 / 32), 256>>>(W_gru, wgh, wgl, 2048, 3072);
    wprep_kernel<<<dim3(1024 / 32, 1024 / 32), 256>>>(W_e1, weh, wel, 1024, 1024);

    for (int t = 0; t < TT; t++) {
        img_kernel<<<BATCH / 16, 256>>>(action, W_img, b_img, g_img, beta_img, t);
        mma_gemm_t<32><<<dim3(3072 / 128, BATCH / 128), 256, MMA_SMEM_32>>>(0);
        gru_kernel<<<BATCH, 256>>>(b_gru, g_gru, beta_gru, out, t);
        mma_gemm_t<16><<<dim3(1024 / 64, BATCH / 128), 256, MMA_SMEM_16>>>(1);
        e2_fused_kernel<<<BATCH / 8, 256>>>(b_e1, g_e1, beta_e1, W_e2, b_e2, out, t);
    }
}

// round 14
// speedup vs baseline: 1.0288x; 1.0288x over previous
#include <cuda_runtime.h>
#include <cuda_bf16.h>
#include <math.h>
#include <cstdint>

// ---------------- problem constants ----------------
#define BATCH 2048
#define TT 30
#define ACT 6
#define STOCH 64
#define DETER 1024
#define HIDDEN 1024
#define OUTW (2*STOCH + DETER)   // 1152
#define KIN (STOCH + ACT)        // 70
#define LN_EPS 1e-5f

// ---------------- device state buffers ----------------
__device__ __align__(16) __nv_bfloat16 g_ahi[(size_t)BATCH * 2048];
__device__ __align__(16) __nv_bfloat16 g_alo[(size_t)BATCH * 2048];
__device__ __align__(16) float g_deter[(size_t)BATCH * DETER];
__device__ __align__(16) float g_stoch[(size_t)BATCH * STOCH];
__device__ __align__(16) float g_parts[(size_t)BATCH * 3072];
__device__ __align__(16) float g_e1raw[(size_t)BATCH * 1024];
__device__ __align__(16) __nv_bfloat16 g_wgru_hi[(size_t)3072 * 2048];
__device__ __align__(16) __nv_bfloat16 g_wgru_lo[(size_t)3072 * 2048];
__device__ __align__(16) __nv_bfloat16 g_we1_hi[(size_t)1024 * 1024];
__device__ __align__(16) __nv_bfloat16 g_we1_lo[(size_t)1024 * 1024];

// ---------------- generic helpers ----------------
__device__ __forceinline__ void blockReduce2(float& s, float& ss, float* red) {
    __syncthreads();
#pragma unroll
    for (int o = 16; o > 0; o >>= 1) {
        s  += __shfl_down_sync(0xffffffffu, s, o);
        ss += __shfl_down_sync(0xffffffffu, ss, o);
    }
    int warp = threadIdx.x >> 5, lane = threadIdx.x & 31;
    if (lane == 0) { red[warp] = s; red[8 + warp] = ss; }
    __syncthreads();
    if (threadIdx.x < 32) {
        float a = lane < 8 ? red[lane] : 0.f;
        float c = lane < 8 ? red[8 + lane] : 0.f;
#pragma unroll
        for (int o = 4; o > 0; o >>= 1) {
            a += __shfl_down_sync(0xffffffffu, a, o);
            c += __shfl_down_sync(0xffffffffu, c, o);
        }
        if (lane == 0) { red[0] = a; red[1] = c; }
    }
    __syncthreads();
    s = red[0]; ss = red[1];
}

__device__ __forceinline__ float elu1(float v) { return v > 0.f ? v : expm1f(v); }
__device__ __forceinline__ float sigmoidf(float v) { return 1.f / (1.f + expf(-v)); }

__device__ __forceinline__ void split_store(float v, __nv_bfloat16* hi, __nv_bfloat16* lo) {
    __nv_bfloat16 h = __float2bfloat16(v);
    *hi = h;
    *lo = __float2bfloat16(v - __bfloat162float(h));
}

__device__ __forceinline__ uint32_t bpack(float a, float b) {
    __nv_bfloat162 t = __floats2bfloat162_rn(a, b);
    return *reinterpret_cast<uint32_t*>(&t);
}

__device__ __forceinline__ void split_store4(const float* v, __nv_bfloat16* hip, __nv_bfloat16* lop) {
    float hf[4], lf[4];
#pragma unroll
    for (int q = 0; q < 4; q++) {
        hf[q] = __bfloat162float(__float2bfloat16(v[q]));
        lf[q] = v[q] - hf[q];
    }
    *reinterpret_cast<uint2*>(hip) = make_uint2(bpack(hf[0], hf[1]), bpack(hf[2], hf[3]));
    *reinterpret_cast<uint2*>(lop) = make_uint2(bpack(lf[0], lf[1]), bpack(lf[2], lf[3]));
}

// ---------------- async-copy + ldmatrix + mma helpers ----------------
__device__ __forceinline__ uint32_t smem_u32(const void* p) {
    return (uint32_t)__cvta_generic_to_shared(p);
}
__device__ __forceinline__ void cpa16(uint32_t dst, const void* src) {
    asm volatile("cp.async.cg.shared.global [%0], [%1], 16;\n" :: "r"(dst), "l"(src));
}
__device__ __forceinline__ void cpa_commit() { asm volatile("cp.async.commit_group;\n" ::: "memory"); }
__device__ __forceinline__ void cpa_wait1()  { asm volatile("cp.async.wait_group 1;\n" ::: "memory"); }
__device__ __forceinline__ void cpa_wait0()  { asm volatile("cp.async.wait_group 0;\n" ::: "memory"); }

#define SWZ64(off) ((off) ^ (((off) >> 3) & 0x30))

__device__ __forceinline__ void ldsm_x4(uint32_t* r, uint32_t addr) {
    asm volatile("ldmatrix.sync.aligned.m8n8.x4.shared.b16 {%0,%1,%2,%3}, [%4];"
                 : "=r"(r[0]), "=r"(r[1]), "=r"(r[2]), "=r"(r[3]) : "r"(addr));
}
__device__ __forceinline__ void mma16816(float* c, const uint32_t* a, uint32_t b0, uint32_t b1) {
    asm volatile(
        "mma.sync.aligned.m16n8k16.row.col.f32.bf16.bf16.f32 "
        "{%0,%1,%2,%3}, {%4,%5,%6,%7}, {%8,%9}, {%0,%1,%2,%3};"
        : "+f"(c[0]), "+f"(c[1]), "+f"(c[2]), "+f"(c[3])
        : "r"(a[0]), "r"(a[1]), "r"(a[2]), "r"(a[3]), "r"(b0), "r"(b1));
}

// ---------------- init ----------------
__global__ void init_kernel() {
    int idx = blockIdx.x * blockDim.x + threadIdx.x;
    if (idx < BATCH * DETER) {
        int r = idx >> 10, c = idx & 1023;
        g_deter[idx] = 0.f;
        g_ahi[(size_t)r * 2048 + 1024 + c] = __float2bfloat16(0.f);
        g_alo[(size_t)r * 2048 + 1024 + c] = __float2bfloat16(0.f);
    }
    if (idx < BATCH * STOCH) g_stoch[idx] = 0.f;
}

// ---------------- weight prep ----------------
__global__ __launch_bounds__(256) void wprep_kernel(
    const float* __restrict__ W, __nv_bfloat16* __restrict__ Whi,
    __nv_bfloat16* __restrict__ Wlo, int K, int N)
{
    __shared__ float s[32][33];
    int tx = threadIdx.x & 31, ty = threadIdx.x >> 5;
    int n0 = blockIdx.x * 32, k0 = blockIdx.y * 32;
#pragma unroll
    for (int j = 0; j < 4; j++)
        s[ty + j * 8][tx] = W[(size_t)(k0 + ty + j * 8) * N + n0 + tx];
    __syncthreads();
#pragma unroll
    for (int j = 0; j < 4; j++) {
        int n = n0 + ty + j * 8;
        int k = k0 + tx;
        float v = s[tx][ty + j * 8];
        __nv_bfloat16 h = __float2bfloat16(v);
        Whi[(size_t)n * K + k] = h;
        Wlo[(size_t)n * K + k] = __float2bfloat16(v - __bfloat162float(h));
    }
}

// ---------------- K1: img layer (R10-proven: 8 rows/block, float4 W loads) ----------------
__global__ __launch_bounds__(256) void img_kernel(
    const float* __restrict__ action, const float* __restrict__ W,
    const float* __restrict__ bvec, const float* __restrict__ gvec,
    const float* __restrict__ beta, int t)
{
    __shared__ float xin[8][72];
    __shared__ float vals[8][1024];
    __shared__ float red[64];
    int tid = threadIdx.x;
    int b0 = blockIdx.x * 8;

    for (int e = tid; e < 8 * KIN; e += 256) {
        int r = e / KIN, k = e % KIN;
        xin[r][k] = (k < STOCH) ? g_stoch[(size_t)(b0 + r) * STOCH + k]
                                : action[(size_t)(b0 + r) * (TT * ACT) + t * ACT + (k - STOCH)];
    }
    __syncthreads();

    {
        int j0 = tid * 4;
        float acc[8][4];
        float4 bv = *reinterpret_cast<const float4*>(&bvec[j0]);
#pragma unroll
        for (int r = 0; r < 8; r++) {
            acc[r][0] = bv.x; acc[r][1] = bv.y; acc[r][2] = bv.z; acc[r][3] = bv.w;
        }
        for (int k = 0; k < KIN; k++) {
            float4 w = *reinterpret_cast<const float4*>(&W[k * 1024 + j0]);
#pragma unroll
            for (int r = 0; r < 8; r++) {
                float xv = xin[r][k];
                acc[r][0] = fmaf(xv, w.x, acc[r][0]);
                acc[r][1] = fmaf(xv, w.y, acc[r][1]);
                acc[r][2] = fmaf(xv, w.z, acc[r][2]);
                acc[r][3] = fmaf(xv, w.w, acc[r][3]);
            }
        }
#pragma unroll
        for (int r = 0; r < 8; r++)
            *reinterpret_cast<float4*>(&vals[r][j0]) =
                make_float4(acc[r][0], acc[r][1], acc[r][2], acc[r][3]);
    }
    __syncthreads();

    for (int r = 0; r < 8; r++) {
        float s = 0.f, ss = 0.f;
#pragma unroll
        for (int jj = 0; jj < 4; jj++) {
            float v = vals[r][tid + jj * 256];
            s += v; ss += v * v;
        }
        blockReduce2(s, ss, red);
        float mean = s * (1.f / 1024.f);
        float rstd = rsqrtf(ss * (1.f / 1024.f) - mean * mean + LN_EPS);
#pragma unroll
        for (int jj = 0; jj < 4; jj++) {
            int j = tid + jj * 256;
            float v = (vals[r][j] - mean) * rstd * gvec[j] + beta[j];
            float x = elu1(v);
            size_t o = (size_t)(b0 + r) * 2048 + j;
            split_store(x, &g_ahi[o], &g_alo[o]);
        }
    }
}

// ---------------- K2: bf16x3 GEMM, per-slab 3-product, templated warp-N ----------------
template<int WN>
__global__ void __launch_bounds__(256, 2) mma_gemm_t(int mode)
{
    constexpr int TN = 4 * WN;
    constexpr int NT = WN / 8;
    constexpr int NF = WN / 16;
    constexpr uint32_t B_BYTES = (uint32_t)TN * 64u;
    constexpr uint32_t STG = 16384u + 2u * B_BYTES;
    constexpr uint32_t T_AHI = 0u, T_ALO = 8192u, T_BHI = 16384u, T_BLO = 16384u + B_BYTES;

    extern __shared__ char smraw[];
    uint32_t base = smem_u32(smraw);

    const __nv_bfloat16 *Ahi, *Alo, *Bhi, *Blo;
    float* C;
    int lda, ldb, ldc, Kseg;
    if (mode == 0) {
        Ahi = g_ahi; Alo = g_alo; lda = 2048; Kseg = 2048;
        Bhi = g_wgru_hi; Blo = g_wgru_lo; ldb = 2048;
        C = g_parts; ldc = 3072;
    } else {
        Ahi = g_ahi + 1024; Alo = g_alo + 1024; lda = 2048; Kseg = 1024;
        Bhi = g_we1_hi; Blo = g_we1_lo; ldb = 1024;
        C = g_e1raw; ldc = 1024;
    }
    const int SLABS = Kseg >> 5;

    int tid = threadIdx.x;
    int wid = tid >> 5, lane = tid & 31;
    int row0 = blockIdx.y * 128;
    int col0 = blockIdx.x * TN;

    float acc[4][NT][4];
#pragma unroll
    for (int i = 0; i < 4; i++)
#pragma unroll
        for (int j = 0; j < NT; j++)
#pragma unroll
            for (int q = 0; q < 4; q++) acc[i][j][q] = 0.f;

    auto load_slab = [&](int s, int buf) {
        int k0 = s << 5;
        uint32_t st = base + (uint32_t)buf * STG;
#pragma unroll
        for (int i = 0; i < 2; i++) {
            int e = tid + i * 256;
            int r = e >> 2, c = e & 3;
            uint32_t so = SWZ64(r * 64 + c * 16);
            cpa16(st + T_AHI + so, Ahi + (size_t)(row0 + r) * lda + k0 + c * 8);
            cpa16(st + T_ALO + so, Alo + (size_t)(row0 + r) * lda + k0 + c * 8);
        }
#pragma unroll
        for (int i = 0; i < TN / 64; i++) {
            int e = tid + i * 256;
            int r = e >> 2, c = e & 3;
            uint32_t so = SWZ64(r * 64 + c * 16);
            cpa16(st + T_BHI + so, Bhi + (size_t)(col0 + r) * ldb + k0 + c * 8);
            cpa16(st + T_BLO + so, Blo + (size_t)(col0 + r) * ldb + k0 + c * 8);
        }
        cpa_commit();
    };

    int m0w = (wid & 1) * 64;
    int n0w = (wid >> 1) * WN;
    int grp = lane >> 3, rin = lane & 7;

    load_slab(0, 0);
    load_slab(1, 1);

    for (int s = 0; s < SLABS; s++) {
        int buf = s % 3;
        if (s + 1 < SLABS) cpa_wait1();
        else               cpa_wait0();
        __syncthreads();
        if (s + 2 < SLABS) load_slab(s + 2, (s + 2) % 3);

        uint32_t st = base + (uint32_t)buf * STG;
#pragma unroll
        for (int kk = 0; kk < 2; kk++) {
            int a_row = rin + (grp & 1) * 8;
            int a_ch  = kk * 2 + (grp >> 1);
            int b_row = rin + (grp >> 1) * 8;
            int b_ch  = kk * 2 + (grp & 1);

            uint32_t bh[NF][4], bl[NF][4];
#pragma unroll
            for (int nt2 = 0; nt2 < NF; nt2++) {
                uint32_t bo = SWZ64((n0w + nt2 * 16 + b_row) * 64 + b_ch * 16);
                ldsm_x4(bh[nt2], st + T_BHI + bo);
                ldsm_x4(bl[nt2], st + T_BLO + bo);
            }
#pragma unroll
            for (int mt = 0; mt < 4; mt++) {
                uint32_t ao = SWZ64((m0w + mt * 16 + a_row) * 64 + a_ch * 16);
                uint32_t ah[4], al[4];
                ldsm_x4(ah, st + T_AHI + ao);
                ldsm_x4(al, st + T_ALO + ao);
#pragma unroll
                for (int nt = 0; nt < NT; nt++) {
                    uint32_t h0 = bh[nt >> 1][(nt & 1) * 2], h1 = bh[nt >> 1][(nt & 1) * 2 + 1];
                    uint32_t l0 = bl[nt >> 1][(nt & 1) * 2], l1 = bl[nt >> 1][(nt & 1) * 2 + 1];
                    mma16816(acc[mt][nt], ah, h0, h1);   // hi*hi
                    mma16816(acc[mt][nt], al, h0, h1);   // lo*hi
                    mma16816(acc[mt][nt], ah, l0, l1);   // hi*lo
                }
            }
        }
    }

#pragma unroll
    for (int mt = 0; mt < 4; mt++) {
        int r0 = row0 + m0w + mt * 16 + (lane >> 2);
#pragma unroll
        for (int nt = 0; nt < NT; nt++) {
            int cc = col0 + n0w + nt * 8 + (lane & 3) * 2;
            *reinterpret_cast<float2*>(&C[(size_t)r0 * ldc + cc]) =
                make_float2(acc[mt][nt][0], acc[mt][nt][1]);
            *reinterpret_cast<float2*>(&C[(size_t)(r0 + 8) * ldc + cc]) =
                make_float2(acc[mt][nt][2], acc[mt][nt][3]);
        }
    }
}

// ---------------- K3: GRU gates (register-resident, float4) ----------------
__global__ __launch_bounds__(256) void gru_kernel(
    const float* __restrict__ bgru, const float* __restrict__ ggru,
    const float* __restrict__ betag, float* __restrict__ out, int t)
{
    __shared__ float red[64];
    int b = blockIdx.x, tid = threadIdx.x;
    const float4* row4 = reinterpret_cast<const float4*>(g_parts + (size_t)b * 3072);
    const float4* bg4  = reinterpret_cast<const float4*>(bgru);

    float4 loc[3];
    float s = 0.f, ss = 0.f;
#pragma unroll
    for (int jj = 0; jj < 3; jj++) {
        float4 x = row4[tid + jj * 256];
        float4 bb = bg4[tid + jj * 256];
        x.x += bb.x; x.y += bb.y; x.z += bb.z; x.w += bb.w;
        loc[jj] = x;
        s += x.x + x.y + x.z + x.w;
        ss += x.x * x.x + x.y * x.y + x.z * x.z + x.w * x.w;
    }
    blockReduce2(s, ss, red);
    float mean = s * (1.f / 3072.f);
    float rstd = rsqrtf(ss * (1.f / 3072.f) - mean * mean + LN_EPS);

    const float4* gg4 = reinterpret_cast<const float4*>(ggru);
    const float4* bt4 = reinterpret_cast<const float4*>(betag);
    float V[3][4];
#pragma unroll
    for (int jj = 0; jj < 3; jj++) {
        float4 g = gg4[tid + jj * 256];
        float4 be = bt4[tid + jj * 256];
        V[jj][0] = (loc[jj].x - mean) * rstd * g.x + be.x;
        V[jj][1] = (loc[jj].y - mean) * rstd * g.y + be.y;
        V[jj][2] = (loc[jj].z - mean) * rstd * g.z + be.z;
        V[jj][3] = (loc[jj].w - mean) * rstd * g.w + be.w;
    }

    float4 dp = *reinterpret_cast<const float4*>(&g_deter[(size_t)b * 1024 + tid * 4]);
    float dpv[4] = {dp.x, dp.y, dp.z, dp.w};
    float dn[4];
#pragma unroll
    for (int q = 0; q < 4; q++) {
        float reset  = sigmoidf(V[0][q]);
        float cand   = tanhf(reset * V[1][q]);
        float update = sigmoidf(V[2][q] - 1.f);
        dn[q] = update * cand + (1.f - update) * dpv[q];
    }
    *reinterpret_cast<float4*>(&g_deter[(size_t)b * 1024 + tid * 4]) =
        make_float4(dn[0], dn[1], dn[2], dn[3]);
    *reinterpret_cast<float4*>(&out[(size_t)b * (TT * OUTW) + (size_t)t * OUTW + 128 + tid * 4]) =
        make_float4(dn[0], dn[1], dn[2], dn[3]);
    size_t o = (size_t)b * 2048 + 1024 + tid * 4;
    split_store4(dn, &g_ahi[o], &g_alo[o]);
}

// ---------------- K6: fused e1-LN/ELU + e2 GEMM + stats (8 rows/block) ----------------
__global__ __launch_bounds__(256) void e2_fused_kernel(
    const float* __restrict__ be1, const float* __restrict__ ge1,
    const float* __restrict__ betae1,
    const float* __restrict__ W, const float* __restrict__ bias,
    float* __restrict__ out, int t)
{
    __shared__ float hs[8][33];
    __shared__ float ws[32][128];
    __shared__ float smean[8], srstd[8];
    int tid = threadIdx.x;
    int r0 = blockIdx.x * 8;
    int w = tid >> 5, lane = tid & 31;

    {
        const float4* row4 = reinterpret_cast<const float4*>(g_e1raw + (size_t)(r0 + w) * 1024);
        const float4* b4 = reinterpret_cast<const float4*>(be1);
        float s = 0.f, ss = 0.f;
#pragma unroll
        for (int i = 0; i < 8; i++) {
            float4 x = row4[lane + i * 32];
            float4 bb = b4[lane + i * 32];
            x.x += bb.x; x.y += bb.y; x.z += bb.z; x.w += bb.w;
            s += x.x + x.y + x.z + x.w;
            ss += x.x * x.x + x.y * x.y + x.z * x.z + x.w * x.w;
        }
#pragma unroll
        for (int o = 16; o > 0; o >>= 1) {
            s  += __shfl_down_sync(0xffffffffu, s, o);
            ss += __shfl_down_sync(0xffffffffu, ss, o);
        }
        if (lane == 0) {
            float mean = s * (1.f / 1024.f);
            smean[w] = mean;
            srstd[w] = rsqrtf(ss * (1.f / 1024.f) - mean * mean + LN_EPS);
        }
    }
    __syncthreads();

    int col = tid & 127, rl = tid >> 7;
    float acc[4];
#pragma unroll
    for (int q = 0; q < 4; q++) acc[q] = 0.f;

    for (int k0 = 0; k0 < 1024; k0 += 32) {
        if (tid < 64) {
            int rr = tid >> 3, k4 = (tid & 7) * 4;
            int c = k0 + k4;
            float4 v = *reinterpret_cast<const float4*>(&g_e1raw[(size_t)(r0 + rr) * 1024 + c]);
            float4 bb = *reinterpret_cast<const float4*>(&be1[c]);
            float4 g  = *reinterpret_cast<const float4*>(&ge1[c]);
            float4 be = *reinterpret_cast<const float4*>(&betae1[c]);
            float mean = smean[rr], rstd = srstd[rr];
            hs[rr][k4]     = elu1(((v.x + bb.x) - mean) * rstd * g.x + be.x);
            hs[rr][k4 + 1] = elu1(((v.y + bb.y) - mean) * rstd * g.y + be.y);
            hs[rr][k4 + 2] = elu1(((v.z + bb.z) - mean) * rstd * g.z + be.z);
            hs[rr][k4 + 3] = elu1(((v.w + bb.w) - mean) * rstd * g.w + be.w);
        }
#pragma unroll
        for (int i = 0; i < 4; i++) {
            int idx = tid + i * 256;
            int kk = idx >> 5, c4 = (idx & 31) * 4;
            float4 v = *reinterpret_cast<const float4*>(&W[(size_t)(k0 + kk) * 128 + c4]);
            ws[kk][c4] = v.x; ws[kk][c4 + 1] = v.y; ws[kk][c4 + 2] = v.z; ws[kk][c4 + 3] = v.w;
        }
        __syncthreads();
#pragma unroll
        for (int kk = 0; kk < 32; kk++) {
            float wv = ws[kk][col];
#pragma unroll
            for (int q = 0; q < 4; q++)
                acc[q] = fmaf(hs[rl + 2 * q][kk], wv, acc[q]);
        }
        __syncthreads();
    }

    float bv = bias[col];
#pragma unroll
    for (int q = 0; q < 4; q++) {
        int r = r0 + rl + 2 * q;
        float sv = acc[q] + bv;
        if (col < 64) {
            g_stoch[(size_t)r * STOCH + col] = sv;
            out[(size_t)r * (TT * OUTW) + (size_t)t * OUTW + col] = sv;
        } else {
            float sp = fmaxf(sv, 0.f) + log1pf(expf(-fabsf(sv)));
            out[(size_t)r * (TT * OUTW) + (size_t)t * OUTW + col] = sp + 0.1f;
        }
    }
}

// ---------------- launcher ----------------
#define MMA_SMEM_32 98304    // 3 x (16384 + 2*8192)
#define MMA_SMEM_16 73728    // 3 x (16384 + 2*4096)

extern "C" void kernel_launch(void* const* d_in, const int* in_sizes, int n_in,
                              void* d_out, int out_size)
{
    const float* action   = (const float*)d_in[0];
    const float* W_img    = (const float*)d_in[1];
    const float* b_img    = (const float*)d_in[2];
    const float* g_img    = (const float*)d_in[3];
    const float* beta_img = (const float*)d_in[4];
    const float* W_gru    = (const float*)d_in[5];
    const float* b_gru    = (const float*)d_in[6];
    const float* g_gru    = (const float*)d_in[7];
    const float* beta_gru = (const float*)d_in[8];
    const float* W_e1     = (const float*)d_in[9];    // [5,1024,1024] -> slice 0
    const float* b_e1     = (const float*)d_in[10];
    const float* g_e1     = (const float*)d_in[11];
    const float* beta_e1  = (const float*)d_in[12];
    const float* W_e2     = (const float*)d_in[13];   // [5,1024,128] -> slice 0
    const float* b_e2     = (const float*)d_in[14];
    float* out = (float*)d_out;

    cudaFuncSetAttribute(mma_gemm_t<32>, cudaFuncAttributeMaxDynamicSharedMemorySize, MMA_SMEM_32);
    cudaFuncSetAttribute(mma_gemm_t<16>, cudaFuncAttributeMaxDynamicSharedMemorySize, MMA_SMEM_16);

    init_kernel<<<(BATCH * DETER + 255) / 256, 256>>>();

    __nv_bfloat16 *wgh, *wgl, *weh, *wel;
    cudaGetSymbolAddress((void**)&wgh, g_wgru_hi);
    cudaGetSymbolAddress((void**)&wgl, g_wgru_lo);
    cudaGetSymbolAddress((void**)&weh, g_we1_hi);
    cudaGetSymbolAddress((void**)&wel, g_we1_lo);
    wprep_kernel<<<dim3(3072 / 32, 2048 / 32), 256>>>(W_gru, wgh, wgl, 2048, 3072);
    wprep_kernel<<<dim3(1024 / 32, 1024 / 32), 256>>>(W_e1, weh, wel, 1024, 1024);

    for (int t = 0; t < TT; t++) {
        img_kernel<<<BATCH / 8, 256>>>(action, W_img, b_img, g_img, beta_img, t);
        mma_gemm_t<32><<<dim3(3072 / 128, BATCH / 128), 256, MMA_SMEM_32>>>(0);
        gru_kernel<<<BATCH, 256>>>(b_gru, g_gru, beta_gru, out, t);
        mma_gemm_t<16><<<dim3(1024 / 64, BATCH / 128), 256, MMA_SMEM_16>>>(1);
        e2_fused_kernel<<<BATCH / 8, 256>>>(b_e1, g_e1, beta_e1, W_e2, b_e2, out, t);
    }
}

// round 16
// speedup vs baseline: 1.0626x; 1.0328x over previous
#include <cuda_runtime.h>
#include <cuda_bf16.h>
#include <math.h>
#include <cstdint>

// ---------------- problem constants ----------------
#define BATCH 2048
#define TT 30
#define ACT 6
#define STOCH 64
#define DETER 1024
#define HIDDEN 1024
#define OUTW (2*STOCH + DETER)   // 1152
#define KIN (STOCH + ACT)        // 70
#define LN_EPS 1e-5f

// ---------------- device state buffers ----------------
__device__ __align__(16) __nv_bfloat16 g_ahi[(size_t)BATCH * 2048];
__device__ __align__(16) __nv_bfloat16 g_alo[(size_t)BATCH * 2048];
__device__ __align__(16) float g_deter[(size_t)BATCH * DETER];
__device__ __align__(16) float g_stoch[(size_t)BATCH * STOCH];
__device__ __align__(16) float g_parts[(size_t)BATCH * 3072];
__device__ __align__(16) float g_e1raw[(size_t)BATCH * 1024];
__device__ __align__(16) __nv_bfloat16 g_wgru_hi[(size_t)3072 * 2048];
__device__ __align__(16) __nv_bfloat16 g_wgru_lo[(size_t)3072 * 2048];
__device__ __align__(16) __nv_bfloat16 g_we1_hi[(size_t)1024 * 1024];
__device__ __align__(16) __nv_bfloat16 g_we1_lo[(size_t)1024 * 1024];

// ---------------- generic helpers ----------------
__device__ __forceinline__ void blockReduce2(float& s, float& ss, float* red) {
    __syncthreads();
#pragma unroll
    for (int o = 16; o > 0; o >>= 1) {
        s  += __shfl_down_sync(0xffffffffu, s, o);
        ss += __shfl_down_sync(0xffffffffu, ss, o);
    }
    int warp = threadIdx.x >> 5, lane = threadIdx.x & 31;
    if (lane == 0) { red[warp] = s; red[8 + warp] = ss; }
    __syncthreads();
    if (threadIdx.x < 32) {
        float a = lane < 8 ? red[lane] : 0.f;
        float c = lane < 8 ? red[8 + lane] : 0.f;
#pragma unroll
        for (int o = 4; o > 0; o >>= 1) {
            a += __shfl_down_sync(0xffffffffu, a, o);
            c += __shfl_down_sync(0xffffffffu, c, o);
        }
        if (lane == 0) { red[0] = a; red[1] = c; }
    }
    __syncthreads();
    s = red[0]; ss = red[1];
}

// fast transcendentals: ex2/rcp approx (rel err ~2^-20, far below 2e-4 calibrated budget)
__device__ __forceinline__ float fsig(float x)  { return __fdividef(1.f, 1.f + __expf(-x)); }
__device__ __forceinline__ float ftanh(float x) { return 1.f - __fdividef(2.f, __expf(2.f * x) + 1.f); }
__device__ __forceinline__ float elu1(float v)  { return v > 0.f ? v : __expf(v) - 1.f; }

__device__ __forceinline__ void split_store(float v, __nv_bfloat16* hi, __nv_bfloat16* lo) {
    __nv_bfloat16 h = __float2bfloat16(v);
    *hi = h;
    *lo = __float2bfloat16(v - __bfloat162float(h));
}

__device__ __forceinline__ uint32_t bpack(float a, float b) {
    __nv_bfloat162 t = __floats2bfloat162_rn(a, b);
    return *reinterpret_cast<uint32_t*>(&t);
}

__device__ __forceinline__ void split_store4(const float* v, __nv_bfloat16* hip, __nv_bfloat16* lop) {
    float hf[4], lf[4];
#pragma unroll
    for (int q = 0; q < 4; q++) {
        hf[q] = __bfloat162float(__float2bfloat16(v[q]));
        lf[q] = v[q] - hf[q];
    }
    *reinterpret_cast<uint2*>(hip) = make_uint2(bpack(hf[0], hf[1]), bpack(hf[2], hf[3]));
    *reinterpret_cast<uint2*>(lop) = make_uint2(bpack(lf[0], lf[1]), bpack(lf[2], lf[3]));
}

// ---------------- async-copy + ldmatrix + mma helpers ----------------
__device__ __forceinline__ uint32_t smem_u32(const void* p) {
    return (uint32_t)__cvta_generic_to_shared(p);
}
__device__ __forceinline__ void cpa16(uint32_t dst, const void* src) {
    asm volatile("cp.async.cg.shared.global [%0], [%1], 16;\n" :: "r"(dst), "l"(src));
}
__device__ __forceinline__ void cpa_commit() { asm volatile("cp.async.commit_group;\n" ::: "memory"); }
__device__ __forceinline__ void cpa_wait1()  { asm volatile("cp.async.wait_group 1;\n" ::: "memory"); }
__device__ __forceinline__ void cpa_wait0()  { asm volatile("cp.async.wait_group 0;\n" ::: "memory"); }

#define SWZ64(off) ((off) ^ (((off) >> 3) & 0x30))

__device__ __forceinline__ void ldsm_x4(uint32_t* r, uint32_t addr) {
    asm volatile("ldmatrix.sync.aligned.m8n8.x4.shared.b16 {%0,%1,%2,%3}, [%4];"
                 : "=r"(r[0]), "=r"(r[1]), "=r"(r[2]), "=r"(r[3]) : "r"(addr));
}
__device__ __forceinline__ void mma16816(float* c, const uint32_t* a, uint32_t b0, uint32_t b1) {
    asm volatile(
        "mma.sync.aligned.m16n8k16.row.col.f32.bf16.bf16.f32 "
        "{%0,%1,%2,%3}, {%4,%5,%6,%7}, {%8,%9}, {%0,%1,%2,%3};"
        : "+f"(c[0]), "+f"(c[1]), "+f"(c[2]), "+f"(c[3])
        : "r"(a[0]), "r"(a[1]), "r"(a[2]), "r"(a[3]), "r"(b0), "r"(b1));
}

// ---------------- init ----------------
__global__ void init_kernel() {
    int idx = blockIdx.x * blockDim.x + threadIdx.x;
    if (idx < BATCH * DETER) {
        int r = idx >> 10, c = idx & 1023;
        g_deter[idx] = 0.f;
        g_ahi[(size_t)r * 2048 + 1024 + c] = __float2bfloat16(0.f);
        g_alo[(size_t)r * 2048 + 1024 + c] = __float2bfloat16(0.f);
    }
    if (idx < BATCH * STOCH) g_stoch[idx] = 0.f;
}

// ---------------- weight prep ----------------
__global__ __launch_bounds__(256) void wprep_kernel(
    const float* __restrict__ W, __nv_bfloat16* __restrict__ Whi,
    __nv_bfloat16* __restrict__ Wlo, int K, int N)
{
    __shared__ float s[32][33];
    int tx = threadIdx.x & 31, ty = threadIdx.x >> 5;
    int n0 = blockIdx.x * 32, k0 = blockIdx.y * 32;
#pragma unroll
    for (int j = 0; j < 4; j++)
        s[ty + j * 8][tx] = W[(size_t)(k0 + ty + j * 8) * N + n0 + tx];
    __syncthreads();
#pragma unroll
    for (int j = 0; j < 4; j++) {
        int n = n0 + ty + j * 8;
        int k = k0 + tx;
        float v = s[tx][ty + j * 8];
        __nv_bfloat16 h = __float2bfloat16(v);
        Whi[(size_t)n * K + k] = h;
        Wlo[(size_t)n * K + k] = __float2bfloat16(v - __bfloat162float(h));
    }
}

// ---------------- shared img body: xin[8][72] -> LN -> ELU -> split store ----------------
__device__ __forceinline__ void img_body(
    float (*xin)[72], float* vals /*[8*1024]*/, float* red,
    const float* __restrict__ W, const float* __restrict__ bvec,
    const float* __restrict__ gvec, const float* __restrict__ beta, int b0)
{
    int tid = threadIdx.x;
    {
        int j0 = tid * 4;
        float acc[8][4];
        float4 bv = *reinterpret_cast<const float4*>(&bvec[j0]);
#pragma unroll
        for (int r = 0; r < 8; r++) {
            acc[r][0] = bv.x; acc[r][1] = bv.y; acc[r][2] = bv.z; acc[r][3] = bv.w;
        }
        for (int k = 0; k < KIN; k++) {
            float4 w = *reinterpret_cast<const float4*>(&W[k * 1024 + j0]);
#pragma unroll
            for (int r = 0; r < 8; r++) {
                float xv = xin[r][k];
                acc[r][0] = fmaf(xv, w.x, acc[r][0]);
                acc[r][1] = fmaf(xv, w.y, acc[r][1]);
                acc[r][2] = fmaf(xv, w.z, acc[r][2]);
                acc[r][3] = fmaf(xv, w.w, acc[r][3]);
            }
        }
#pragma unroll
        for (int r = 0; r < 8; r++)
            *reinterpret_cast<float4*>(&vals[r * 1024 + j0]) =
                make_float4(acc[r][0], acc[r][1], acc[r][2], acc[r][3]);
    }
    __syncthreads();

    for (int r = 0; r < 8; r++) {
        float s = 0.f, ss = 0.f;
#pragma unroll
        for (int jj = 0; jj < 4; jj++) {
            float v = vals[r * 1024 + tid + jj * 256];
            s += v; ss += v * v;
        }
        blockReduce2(s, ss, red);
        float mean = s * (1.f / 1024.f);
        float rstd = rsqrtf(ss * (1.f / 1024.f) - mean * mean + LN_EPS);
#pragma unroll
        for (int jj = 0; jj < 4; jj++) {
            int j = tid + jj * 256;
            float v = (vals[r * 1024 + j] - mean) * rstd * gvec[j] + beta[j];
            float x = elu1(v);
            size_t o = (size_t)(b0 + r) * 2048 + j;
            split_store(x, &g_ahi[o], &g_alo[o]);
        }
    }
}

// ---------------- K1: standalone img (t=0 only; reads g_stoch zeros) ----------------
__global__ __launch_bounds__(256) void img_kernel(
    const float* __restrict__ action, const float* __restrict__ W,
    const float* __restrict__ bvec, const float* __restrict__ gvec,
    const float* __restrict__ beta, int t)
{
    __shared__ float xin[8][72];
    __shared__ float red[64];
    extern __shared__ float vals[];   // [8*1024]
    int tid = threadIdx.x;
    int b0 = blockIdx.x * 8;

    for (int e = tid; e < 8 * KIN; e += 256) {
        int r = e / KIN, k = e % KIN;
        xin[r][k] = (k < STOCH) ? g_stoch[(size_t)(b0 + r) * STOCH + k]
                                : action[(size_t)(b0 + r) * (TT * ACT) + t * ACT + (k - STOCH)];
    }
    __syncthreads();
    img_body(xin, vals, red, W, bvec, gvec, beta, b0);
}

// ---------------- K2: bf16x3 GEMM, per-slab 3-product, templated warp-N ----------------
template<int WN>
__global__ void __launch_bounds__(256, 2) mma_gemm_t(int mode)
{
    constexpr int TN = 4 * WN;
    constexpr int NT = WN / 8;
    constexpr int NF = WN / 16;
    constexpr uint32_t B_BYTES = (uint32_t)TN * 64u;
    constexpr uint32_t STG = 16384u + 2u * B_BYTES;
    constexpr uint32_t T_AHI = 0u, T_ALO = 8192u, T_BHI = 16384u, T_BLO = 16384u + B_BYTES;

    extern __shared__ char smraw[];
    uint32_t base = smem_u32(smraw);

    const __nv_bfloat16 *Ahi, *Alo, *Bhi, *Blo;
    float* C;
    int lda, ldb, ldc, Kseg;
    if (mode == 0) {
        Ahi = g_ahi; Alo = g_alo; lda = 2048; Kseg = 2048;
        Bhi = g_wgru_hi; Blo = g_wgru_lo; ldb = 2048;
        C = g_parts; ldc = 3072;
    } else {
        Ahi = g_ahi + 1024; Alo = g_alo + 1024; lda = 2048; Kseg = 1024;
        Bhi = g_we1_hi; Blo = g_we1_lo; ldb = 1024;
        C = g_e1raw; ldc = 1024;
    }
    const int SLABS = Kseg >> 5;

    int tid = threadIdx.x;
    int wid = tid >> 5, lane = tid & 31;
    int row0 = blockIdx.y * 128;
    int col0 = blockIdx.x * TN;

    float acc[4][NT][4];
#pragma unroll
    for (int i = 0; i < 4; i++)
#pragma unroll
        for (int j = 0; j < NT; j++)
#pragma unroll
            for (int q = 0; q < 4; q++) acc[i][j][q] = 0.f;

    auto load_slab = [&](int s, int buf) {
        int k0 = s << 5;
        uint32_t st = base + (uint32_t)buf * STG;
#pragma unroll
        for (int i = 0; i < 2; i++) {
            int e = tid + i * 256;
            int r = e >> 2, c = e & 3;
            uint32_t so = SWZ64(r * 64 + c * 16);
            cpa16(st + T_AHI + so, Ahi + (size_t)(row0 + r) * lda + k0 + c * 8);
            cpa16(st + T_ALO + so, Alo + (size_t)(row0 + r) * lda + k0 + c * 8);
        }
#pragma unroll
        for (int i = 0; i < TN / 64; i++) {
            int e = tid + i * 256;
            int r = e >> 2, c = e & 3;
            uint32_t so = SWZ64(r * 64 + c * 16);
            cpa16(st + T_BHI + so, Bhi + (size_t)(col0 + r) * ldb + k0 + c * 8);
            cpa16(st + T_BLO + so, Blo + (size_t)(col0 + r) * ldb + k0 + c * 8);
        }
        cpa_commit();
    };

    int m0w = (wid & 1) * 64;
    int n0w = (wid >> 1) * WN;
    int grp = lane >> 3, rin = lane & 7;

    load_slab(0, 0);
    load_slab(1, 1);

    for (int s = 0; s < SLABS; s++) {
        int buf = s % 3;
        if (s + 1 < SLABS) cpa_wait1();
        else               cpa_wait0();
        __syncthreads();
        if (s + 2 < SLABS) load_slab(s + 2, (s + 2) % 3);

        uint32_t st = base + (uint32_t)buf * STG;
#pragma unroll
        for (int kk = 0; kk < 2; kk++) {
            int a_row = rin + (grp & 1) * 8;
            int a_ch  = kk * 2 + (grp >> 1);
            int b_row = rin + (grp >> 1) * 8;
            int b_ch  = kk * 2 + (grp & 1);

            uint32_t bh[NF][4], bl[NF][4];
#pragma unroll
            for (int nt2 = 0; nt2 < NF; nt2++) {
                uint32_t bo = SWZ64((n0w + nt2 * 16 + b_row) * 64 + b_ch * 16);
                ldsm_x4(bh[nt2], st + T_BHI + bo);
                ldsm_x4(bl[nt2], st + T_BLO + bo);
            }
#pragma unroll
            for (int mt = 0; mt < 4; mt++) {
                uint32_t ao = SWZ64((m0w + mt * 16 + a_row) * 64 + a_ch * 16);
                uint32_t ah[4], al[4];
                ldsm_x4(ah, st + T_AHI + ao);
                ldsm_x4(al, st + T_ALO + ao);
#pragma unroll
                for (int nt = 0; nt < NT; nt++) {
                    uint32_t h0 = bh[nt >> 1][(nt & 1) * 2], h1 = bh[nt >> 1][(nt & 1) * 2 + 1];
                    uint32_t l0 = bl[nt >> 1][(nt & 1) * 2], l1 = bl[nt >> 1][(nt & 1) * 2 + 1];
                    mma16816(acc[mt][nt], ah, h0, h1);   // hi*hi
                    mma16816(acc[mt][nt], al, h0, h1);   // lo*hi
                    mma16816(acc[mt][nt], ah, l0, l1);   // hi*lo
                }
            }
        }
    }

#pragma unroll
    for (int mt = 0; mt < 4; mt++) {
        int r0 = row0 + m0w + mt * 16 + (lane >> 2);
#pragma unroll
        for (int nt = 0; nt < NT; nt++) {
            int cc = col0 + n0w + nt * 8 + (lane & 3) * 2;
            *reinterpret_cast<float2*>(&C[(size_t)r0 * ldc + cc]) =
                make_float2(acc[mt][nt][0], acc[mt][nt][1]);
            *reinterpret_cast<float2*>(&C[(size_t)(r0 + 8) * ldc + cc]) =
                make_float2(acc[mt][nt][2], acc[mt][nt][3]);
        }
    }
}

// ---------------- K3: GRU gates (register-resident, float4, fast gates) ----------------
__global__ __launch_bounds__(256) void gru_kernel(
    const float* __restrict__ bgru, const float* __restrict__ ggru,
    const float* __restrict__ betag, float* __restrict__ out, int t)
{
    __shared__ float red[64];
    int b = blockIdx.x, tid = threadIdx.x;
    const float4* row4 = reinterpret_cast<const float4*>(g_parts + (size_t)b * 3072);
    const float4* bg4  = reinterpret_cast<const float4*>(bgru);

    float4 loc[3];
    float s = 0.f, ss = 0.f;
#pragma unroll
    for (int jj = 0; jj < 3; jj++) {
        float4 x = row4[tid + jj * 256];
        float4 bb = bg4[tid + jj * 256];
        x.x += bb.x; x.y += bb.y; x.z += bb.z; x.w += bb.w;
        loc[jj] = x;
        s += x.x + x.y + x.z + x.w;
        ss += x.x * x.x + x.y * x.y + x.z * x.z + x.w * x.w;
    }
    blockReduce2(s, ss, red);
    float mean = s * (1.f / 3072.f);
    float rstd = rsqrtf(ss * (1.f / 3072.f) - mean * mean + LN_EPS);

    const float4* gg4 = reinterpret_cast<const float4*>(ggru);
    const float4* bt4 = reinterpret_cast<const float4*>(betag);
    float V[3][4];
#pragma unroll
    for (int jj = 0; jj < 3; jj++) {
        float4 g = gg4[tid + jj * 256];
        float4 be = bt4[tid + jj * 256];
        V[jj][0] = (loc[jj].x - mean) * rstd * g.x + be.x;
        V[jj][1] = (loc[jj].y - mean) * rstd * g.y + be.y;
        V[jj][2] = (loc[jj].z - mean) * rstd * g.z + be.z;
        V[jj][3] = (loc[jj].w - mean) * rstd * g.w + be.w;
    }

    float4 dp = *reinterpret_cast<const float4*>(&g_deter[(size_t)b * 1024 + tid * 4]);
    float dpv[4] = {dp.x, dp.y, dp.z, dp.w};
    float dn[4];
#pragma unroll
    for (int q = 0; q < 4; q++) {
        float reset  = fsig(V[0][q]);
        float cand   = ftanh(reset * V[1][q]);
        float update = fsig(V[2][q] - 1.f);
        dn[q] = update * cand + (1.f - update) * dpv[q];
    }
    *reinterpret_cast<float4*>(&g_deter[(size_t)b * 1024 + tid * 4]) =
        make_float4(dn[0], dn[1], dn[2], dn[3]);
    *reinterpret_cast<float4*>(&out[(size_t)b * (TT * OUTW) + (size_t)t * OUTW + 128 + tid * 4]) =
        make_float4(dn[0], dn[1], dn[2], dn[3]);
    size_t o = (size_t)b * 2048 + 1024 + tid * 4;
    split_store4(dn, &g_ahi[o], &g_alo[o]);
}

// ---------------- K6: fused e1-LN/ELU + e2 GEMM + stats + img(t+1) ----------------
// 256 blocks x 256 threads, 8 rows each. Dynamic smem 32KB aliased: e2 phase uses
// first 16KB as ws[32][128]; img phase uses all 32KB as vals[8][1024].
__global__ __launch_bounds__(256) void e2img_kernel(
    const float* __restrict__ be1, const float* __restrict__ ge1,
    const float* __restrict__ betae1,
    const float* __restrict__ W, const float* __restrict__ bias,
    const float* __restrict__ action, const float* __restrict__ Wimg,
    const float* __restrict__ bimg, const float* __restrict__ gimg,
    const float* __restrict__ betaimg,
    float* __restrict__ out, int t, int do_img)
{
    extern __shared__ float dsm[];           // 32KB: ws (e2 phase) / vals (img phase)
    __shared__ float hs[8][33];
    __shared__ float xin[8][72];             // stoch cols 0..63 filled by e2 epilogue
    __shared__ float red[64];
    __shared__ float smean[8], srstd[8];
    int tid = threadIdx.x;
    int r0 = blockIdx.x * 8;
    int w = tid >> 5, lane = tid & 31;

    // phase 1: warp-per-row LN stats of e1raw
    {
        const float4* row4 = reinterpret_cast<const float4*>(g_e1raw + (size_t)(r0 + w) * 1024);
        const float4* b4 = reinterpret_cast<const float4*>(be1);
        float s = 0.f, ss = 0.f;
#pragma unroll
        for (int i = 0; i < 8; i++) {
            float4 x = row4[lane + i * 32];
            float4 bb = b4[lane + i * 32];
            x.x += bb.x; x.y += bb.y; x.z += bb.z; x.w += bb.w;
            s += x.x + x.y + x.z + x.w;
            ss += x.x * x.x + x.y * x.y + x.z * x.z + x.w * x.w;
        }
#pragma unroll
        for (int o = 16; o > 0; o >>= 1) {
            s  += __shfl_down_sync(0xffffffffu, s, o);
            ss += __shfl_down_sync(0xffffffffu, ss, o);
        }
        if (lane == 0) {
            float mean = s * (1.f / 1024.f);
            smean[w] = mean;
            srstd[w] = rsqrtf(ss * (1.f / 1024.f) - mean * mean + LN_EPS);
        }
    }
    __syncthreads();

    // phase 2: e2 GEMM with on-the-fly LN+ELU
    int col = tid & 127, rl = tid >> 7;
    float acc[4];
#pragma unroll
    for (int q = 0; q < 4; q++) acc[q] = 0.f;

    for (int k0 = 0; k0 < 1024; k0 += 32) {
        if (tid < 64) {
            int rr = tid >> 3, k4 = (tid & 7) * 4;
            int c = k0 + k4;
            float4 v = *reinterpret_cast<const float4*>(&g_e1raw[(size_t)(r0 + rr) * 1024 + c]);
            float4 bb = *reinterpret_cast<const float4*>(&be1[c]);
            float4 g  = *reinterpret_cast<const float4*>(&ge1[c]);
            float4 be = *reinterpret_cast<const float4*>(&betae1[c]);
            float mean = smean[rr], rstd = srstd[rr];
            hs[rr][k4]     = elu1(((v.x + bb.x) - mean) * rstd * g.x + be.x);
            hs[rr][k4 + 1] = elu1(((v.y + bb.y) - mean) * rstd * g.y + be.y);
            hs[rr][k4 + 2] = elu1(((v.z + bb.z) - mean) * rstd * g.z + be.z);
            hs[rr][k4 + 3] = elu1(((v.w + bb.w) - mean) * rstd * g.w + be.w);
        }
#pragma unroll
        for (int i = 0; i < 4; i++) {
            int idx = tid + i * 256;
            int kk = idx >> 5, c4 = (idx & 31) * 4;
            float4 v = *reinterpret_cast<const float4*>(&W[(size_t)(k0 + kk) * 128 + c4]);
            dsm[kk * 128 + c4]     = v.x;
            dsm[kk * 128 + c4 + 1] = v.y;
            dsm[kk * 128 + c4 + 2] = v.z;
            dsm[kk * 128 + c4 + 3] = v.w;
        }
        __syncthreads();
#pragma unroll
        for (int kk = 0; kk < 32; kk++) {
            float wv = dsm[kk * 128 + col];
#pragma unroll
            for (int q = 0; q < 4; q++)
                acc[q] = fmaf(hs[rl + 2 * q][kk], wv, acc[q]);
        }
        __syncthreads();
    }

    // phase 3: stats epilogue; stoch -> xin for img
    float bv = bias[col];
#pragma unroll
    for (int q = 0; q < 4; q++) {
        int r = r0 + rl + 2 * q;
        float sv = acc[q] + bv;
        if (col < 64) {
            xin[rl + 2 * q][col] = sv;
            out[(size_t)r * (TT * OUTW) + (size_t)t * OUTW + col] = sv;
        } else {
            float sp = fmaxf(sv, 0.f) + __logf(1.f + __expf(-fabsf(sv)));
            out[(size_t)r * (TT * OUTW) + (size_t)t * OUTW + col] = sp + 0.1f;
        }
    }

    // phase 4: img(t+1) for the same 8 rows
    if (do_img) {
        for (int e = tid; e < 8 * ACT; e += 256) {
            int r = e / ACT, c = e % ACT;
            xin[r][STOCH + c] = action[(size_t)(r0 + r) * (TT * ACT) + (t + 1) * ACT + c];
        }
        __syncthreads();
        img_body(xin, dsm, red, Wimg, bimg, gimg, betaimg, r0);
    }
}

// ---------------- launcher ----------------
#define MMA_SMEM_32 98304    // 3 x (16384 + 2*8192)
#define MMA_SMEM_16 73728    // 3 x (16384 + 2*4096)
#define IMG_DSM     32768

extern "C" void kernel_launch(void* const* d_in, const int* in_sizes, int n_in,
                              void* d_out, int out_size)
{
    const float* action   = (const float*)d_in[0];
    const float* W_img    = (const float*)d_in[1];
    const float* b_img    = (const float*)d_in[2];
    const float* g_img    = (const float*)d_in[3];
    const float* beta_img = (const float*)d_in[4];
    const float* W_gru    = (const float*)d_in[5];
    const float* b_gru    = (const float*)d_in[6];
    const float* g_gru    = (const float*)d_in[7];
    const float* beta_gru = (const float*)d_in[8];
    const float* W_e1     = (const float*)d_in[9];    // [5,1024,1024] -> slice 0
    const float* b_e1     = (const float*)d_in[10];
    const float* g_e1     = (const float*)d_in[11];
    const float* beta_e1  = (const float*)d_in[12];
    const float* W_e2     = (const float*)d_in[13];   // [5,1024,128] -> slice 0
    const float* b_e2     = (const float*)d_in[14];
    float* out = (float*)d_out;

    cudaFuncSetAttribute(mma_gemm_t<32>, cudaFuncAttributeMaxDynamicSharedMemorySize, MMA_SMEM_32);
    cudaFuncSetAttribute(mma_gemm_t<16>, cudaFuncAttributeMaxDynamicSharedMemorySize, MMA_SMEM_16);

    init_kernel<<<(BATCH * DETER + 255) / 256, 256>>>();

    __nv_bfloat16 *wgh, *wgl, *weh, *wel;
    cudaGetSymbolAddress((void**)&wgh, g_wgru_hi);
    cudaGetSymbolAddress((void**)&wgl, g_wgru_lo);
    cudaGetSymbolAddress((void**)&weh, g_we1_hi);
    cudaGetSymbolAddress((void**)&wel, g_we1_lo);
    wprep_kernel<<<dim3(3072 / 32, 2048 / 32), 256>>>(W_gru, wgh, wgl, 2048, 3072);
    wprep_kernel<<<dim3(1024 / 32, 1024 / 32), 256>>>(W_e1, weh, wel, 1024, 1024);

    // t=0 img (stoch = 0)
    img_kernel<<<BATCH / 8, 256, IMG_DSM>>>(action, W_img, b_img, g_img, beta_img, 0);

    for (int t = 0; t < TT; t++) {
        mma_gemm_t<32><<<dim3(3072 / 128, BATCH / 128), 256, MMA_SMEM_32>>>(0);
        gru_kernel<<<BATCH, 256>>>(b_gru, g_gru, beta_gru, out, t);
        mma_gemm_t<16><<<dim3(1024 / 64, BATCH / 128), 256, MMA_SMEM_16>>>(1);
        e2img_kernel<<<BATCH / 8, 256, IMG_DSM>>>(
            b_e1, g_e1, beta_e1, W_e2, b_e2,
            action, W_img, b_img, g_img, beta_img,
            out, t, (t + 1 < TT) ? 1 : 0);
    }
}

// round 17
// speedup vs baseline: 1.1302x; 1.0637x over previous
#include <cuda_runtime.h>
#include <cuda_bf16.h>
#include <math.h>
#include <cstdint>

// ---------------- problem constants ----------------
#define BATCH 2048
#define TT 30
#define ACT 6
#define STOCH 64
#define DETER 1024
#define HIDDEN 1024
#define OUTW (2*STOCH + DETER)   // 1152
#define KIN (STOCH + ACT)        // 70
#define LN_EPS 1e-5f

// ---------------- device state buffers ----------------
__device__ __align__(16) __nv_bfloat16 g_ahi[(size_t)BATCH * 2048];
__device__ __align__(16) __nv_bfloat16 g_alo[(size_t)BATCH * 2048];
__device__ __align__(16) float g_deter[(size_t)BATCH * DETER];
__device__ __align__(16) float g_stoch[(size_t)BATCH * STOCH];
__device__ __align__(16) float g_parts[(size_t)BATCH * 3072];
__device__ __align__(16) float g_e1raw[(size_t)BATCH * 1024];
__device__ __align__(16) __nv_bfloat16 g_wgru_hi[(size_t)3072 * 2048];
__device__ __align__(16) __nv_bfloat16 g_wgru_lo[(size_t)3072 * 2048];
__device__ __align__(16) __nv_bfloat16 g_we1_hi[(size_t)1024 * 1024];
__device__ __align__(16) __nv_bfloat16 g_we1_lo[(size_t)1024 * 1024];

// ---------------- generic helpers ----------------
__device__ __forceinline__ void blockReduce2(float& s, float& ss, float* red) {
    __syncthreads();
#pragma unroll
    for (int o = 16; o > 0; o >>= 1) {
        s  += __shfl_down_sync(0xffffffffu, s, o);
        ss += __shfl_down_sync(0xffffffffu, ss, o);
    }
    int warp = threadIdx.x >> 5, lane = threadIdx.x & 31;
    if (lane == 0) { red[warp] = s; red[8 + warp] = ss; }
    __syncthreads();
    if (threadIdx.x < 32) {
        float a = lane < 8 ? red[lane] : 0.f;
        float c = lane < 8 ? red[8 + lane] : 0.f;
#pragma unroll
        for (int o = 4; o > 0; o >>= 1) {
            a += __shfl_down_sync(0xffffffffu, a, o);
            c += __shfl_down_sync(0xffffffffu, c, o);
        }
        if (lane == 0) { red[0] = a; red[1] = c; }
    }
    __syncthreads();
    s = red[0]; ss = red[1];
}

// fast transcendentals (rel err ~2^-20, far below 2e-4 calibrated budget)
__device__ __forceinline__ float fsig(float x)  { return __fdividef(1.f, 1.f + __expf(-x)); }
__device__ __forceinline__ float ftanh(float x) { return 1.f - __fdividef(2.f, __expf(2.f * x) + 1.f); }
__device__ __forceinline__ float elu1(float v)  { return v > 0.f ? v : __expf(v) - 1.f; }

__device__ __forceinline__ void split_store(float v, __nv_bfloat16* hi, __nv_bfloat16* lo) {
    __nv_bfloat16 h = __float2bfloat16(v);
    *hi = h;
    *lo = __float2bfloat16(v - __bfloat162float(h));
}

__device__ __forceinline__ uint32_t bpack(float a, float b) {
    __nv_bfloat162 t = __floats2bfloat162_rn(a, b);
    return *reinterpret_cast<uint32_t*>(&t);
}

__device__ __forceinline__ void split_store4(const float* v, __nv_bfloat16* hip, __nv_bfloat16* lop) {
    float hf[4], lf[4];
#pragma unroll
    for (int q = 0; q < 4; q++) {
        hf[q] = __bfloat162float(__float2bfloat16(v[q]));
        lf[q] = v[q] - hf[q];
    }
    *reinterpret_cast<uint2*>(hip) = make_uint2(bpack(hf[0], hf[1]), bpack(hf[2], hf[3]));
    *reinterpret_cast<uint2*>(lop) = make_uint2(bpack(lf[0], lf[1]), bpack(lf[2], lf[3]));
}

// ---------------- async-copy + ldmatrix + mma helpers ----------------
__device__ __forceinline__ uint32_t smem_u32(const void* p) {
    return (uint32_t)__cvta_generic_to_shared(p);
}
__device__ __forceinline__ void cpa16(uint32_t dst, const void* src) {
    asm volatile("cp.async.cg.shared.global [%0], [%1], 16;\n" :: "r"(dst), "l"(src));
}
__device__ __forceinline__ void cpa_commit() { asm volatile("cp.async.commit_group;\n" ::: "memory"); }
__device__ __forceinline__ void cpa_wait1()  { asm volatile("cp.async.wait_group 1;\n" ::: "memory"); }
__device__ __forceinline__ void cpa_wait0()  { asm volatile("cp.async.wait_group 0;\n" ::: "memory"); }

#define SWZ64(off) ((off) ^ (((off) >> 3) & 0x30))

__device__ __forceinline__ void ldsm_x4(uint32_t* r, uint32_t addr) {
    asm volatile("ldmatrix.sync.aligned.m8n8.x4.shared.b16 {%0,%1,%2,%3}, [%4];"
                 : "=r"(r[0]), "=r"(r[1]), "=r"(r[2]), "=r"(r[3]) : "r"(addr));
}
__device__ __forceinline__ void mma16816(float* c, const uint32_t* a, uint32_t b0, uint32_t b1) {
    asm volatile(
        "mma.sync.aligned.m16n8k16.row.col.f32.bf16.bf16.f32 "
        "{%0,%1,%2,%3}, {%4,%5,%6,%7}, {%8,%9}, {%0,%1,%2,%3};"
        : "+f"(c[0]), "+f"(c[1]), "+f"(c[2]), "+f"(c[3])
        : "r"(a[0]), "r"(a[1]), "r"(a[2]), "r"(a[3]), "r"(b0), "r"(b1));
}

// ---------------- init ----------------
__global__ void init_kernel() {
    int idx = blockIdx.x * blockDim.x + threadIdx.x;
    if (idx < BATCH * DETER) {
        int r = idx >> 10, c = idx & 1023;
        g_deter[idx] = 0.f;
        g_ahi[(size_t)r * 2048 + 1024 + c] = __float2bfloat16(0.f);
        g_alo[(size_t)r * 2048 + 1024 + c] = __float2bfloat16(0.f);
    }
    if (idx < BATCH * STOCH) g_stoch[idx] = 0.f;
}

// ---------------- weight prep ----------------
__global__ __launch_bounds__(256) void wprep_kernel(
    const float* __restrict__ W, __nv_bfloat16* __restrict__ Whi,
    __nv_bfloat16* __restrict__ Wlo, int K, int N)
{
    __shared__ float s[32][33];
    int tx = threadIdx.x & 31, ty = threadIdx.x >> 5;
    int n0 = blockIdx.x * 32, k0 = blockIdx.y * 32;
#pragma unroll
    for (int j = 0; j < 4; j++)
        s[ty + j * 8][tx] = W[(size_t)(k0 + ty + j * 8) * N + n0 + tx];
    __syncthreads();
#pragma unroll
    for (int j = 0; j < 4; j++) {
        int n = n0 + ty + j * 8;
        int k = k0 + tx;
        float v = s[tx][ty + j * 8];
        __nv_bfloat16 h = __float2bfloat16(v);
        Whi[(size_t)n * K + k] = h;
        Wlo[(size_t)n * K + k] = __float2bfloat16(v - __bfloat162float(h));
    }
}

// ---------------- shared img body: xin[8][72] -> LN -> ELU -> split store ----------------
__device__ __forceinline__ void img_body(
    float (*xin)[72], float* vals /*[8*1024]*/, float* red,
    const float* __restrict__ W, const float* __restrict__ bvec,
    const float* __restrict__ gvec, const float* __restrict__ beta, int b0)
{
    int tid = threadIdx.x;
    {
        int j0 = tid * 4;
        float acc[8][4];
        float4 bv = *reinterpret_cast<const float4*>(&bvec[j0]);
#pragma unroll
        for (int r = 0; r < 8; r++) {
            acc[r][0] = bv.x; acc[r][1] = bv.y; acc[r][2] = bv.z; acc[r][3] = bv.w;
        }
        for (int k = 0; k < KIN; k++) {
            float4 w = *reinterpret_cast<const float4*>(&W[k * 1024 + j0]);
#pragma unroll
            for (int r = 0; r < 8; r++) {
                float xv = xin[r][k];
                acc[r][0] = fmaf(xv, w.x, acc[r][0]);
                acc[r][1] = fmaf(xv, w.y, acc[r][1]);
                acc[r][2] = fmaf(xv, w.z, acc[r][2]);
                acc[r][3] = fmaf(xv, w.w, acc[r][3]);
            }
        }
#pragma unroll
        for (int r = 0; r < 8; r++)
            *reinterpret_cast<float4*>(&vals[r * 1024 + j0]) =
                make_float4(acc[r][0], acc[r][1], acc[r][2], acc[r][3]);
    }
    __syncthreads();

    for (int r = 0; r < 8; r++) {
        float s = 0.f, ss = 0.f;
#pragma unroll
        for (int jj = 0; jj < 4; jj++) {
            float v = vals[r * 1024 + tid + jj * 256];
            s += v; ss += v * v;
        }
        blockReduce2(s, ss, red);
        float mean = s * (1.f / 1024.f);
        float rstd = rsqrtf(ss * (1.f / 1024.f) - mean * mean + LN_EPS);
#pragma unroll
        for (int jj = 0; jj < 4; jj++) {
            int j = tid + jj * 256;
            float v = (vals[r * 1024 + j] - mean) * rstd * gvec[j] + beta[j];
            float x = elu1(v);
            size_t o = (size_t)(b0 + r) * 2048 + j;
            split_store(x, &g_ahi[o], &g_alo[o]);
        }
    }
}

// ---------------- K1: standalone img (t=0 only; reads g_stoch zeros) ----------------
__global__ __launch_bounds__(256) void img_kernel(
    const float* __restrict__ action, const float* __restrict__ W,
    const float* __restrict__ bvec, const float* __restrict__ gvec,
    const float* __restrict__ beta, int t)
{
    __shared__ float xin[8][72];
    __shared__ float red[64];
    extern __shared__ float vals[];   // [8*1024]
    int tid = threadIdx.x;
    int b0 = blockIdx.x * 8;

    for (int e = tid; e < 8 * KIN; e += 256) {
        int r = e / KIN, k = e % KIN;
        xin[r][k] = (k < STOCH) ? g_stoch[(size_t)(b0 + r) * STOCH + k]
                                : action[(size_t)(b0 + r) * (TT * ACT) + t * ACT + (k - STOCH)];
    }
    __syncthreads();
    img_body(xin, vals, red, W, bvec, gvec, beta, b0);
}

// ---------------- K2: bf16x3 GEMM, per-slab 3-product, templated warp-N ----------------
template<int WN>
__global__ void __launch_bounds__(256, 2) mma_gemm_t(int mode)
{
    constexpr int TN = 4 * WN;
    constexpr int NT = WN / 8;
    constexpr int NF = WN / 16;
    constexpr uint32_t B_BYTES = (uint32_t)TN * 64u;
    constexpr uint32_t STG = 16384u + 2u * B_BYTES;
    constexpr uint32_t T_AHI = 0u, T_ALO = 8192u, T_BHI = 16384u, T_BLO = 16384u + B_BYTES;

    extern __shared__ char smraw[];
    uint32_t base = smem_u32(smraw);

    const __nv_bfloat16 *Ahi, *Alo, *Bhi, *Blo;
    float* C;
    int lda, ldb, ldc, Kseg;
    if (mode == 0) {
        Ahi = g_ahi; Alo = g_alo; lda = 2048; Kseg = 2048;
        Bhi = g_wgru_hi; Blo = g_wgru_lo; ldb = 2048;
        C = g_parts; ldc = 3072;
    } else {
        Ahi = g_ahi + 1024; Alo = g_alo + 1024; lda = 2048; Kseg = 1024;
        Bhi = g_we1_hi; Blo = g_we1_lo; ldb = 1024;
        C = g_e1raw; ldc = 1024;
    }
    const int SLABS = Kseg >> 5;

    int tid = threadIdx.x;
    int wid = tid >> 5, lane = tid & 31;
    int row0 = blockIdx.y * 128;
    int col0 = blockIdx.x * TN;

    float acc[4][NT][4];
#pragma unroll
    for (int i = 0; i < 4; i++)
#pragma unroll
        for (int j = 0; j < NT; j++)
#pragma unroll
            for (int q = 0; q < 4; q++) acc[i][j][q] = 0.f;

    auto load_slab = [&](int s, int buf) {
        int k0 = s << 5;
        uint32_t st = base + (uint32_t)buf * STG;
#pragma unroll
        for (int i = 0; i < 2; i++) {
            int e = tid + i * 256;
            int r = e >> 2, c = e & 3;
            uint32_t so = SWZ64(r * 64 + c * 16);
            cpa16(st + T_AHI + so, Ahi + (size_t)(row0 + r) * lda + k0 + c * 8);
            cpa16(st + T_ALO + so, Alo + (size_t)(row0 + r) * lda + k0 + c * 8);
        }
#pragma unroll
        for (int i = 0; i < TN / 64; i++) {
            int e = tid + i * 256;
            int r = e >> 2, c = e & 3;
            uint32_t so = SWZ64(r * 64 + c * 16);
            cpa16(st + T_BHI + so, Bhi + (size_t)(col0 + r) * ldb + k0 + c * 8);
            cpa16(st + T_BLO + so, Blo + (size_t)(col0 + r) * ldb + k0 + c * 8);
        }
        cpa_commit();
    };

    int m0w = (wid & 1) * 64;
    int n0w = (wid >> 1) * WN;
    int grp = lane >> 3, rin = lane & 7;

    load_slab(0, 0);
    load_slab(1, 1);

    for (int s = 0; s < SLABS; s++) {
        int buf = s % 3;
        if (s + 1 < SLABS) cpa_wait1();
        else               cpa_wait0();
        __syncthreads();
        if (s + 2 < SLABS) load_slab(s + 2, (s + 2) % 3);

        uint32_t st = base + (uint32_t)buf * STG;
#pragma unroll
        for (int kk = 0; kk < 2; kk++) {
            int a_row = rin + (grp & 1) * 8;
            int a_ch  = kk * 2 + (grp >> 1);
            int b_row = rin + (grp >> 1) * 8;
            int b_ch  = kk * 2 + (grp & 1);

            uint32_t bh[NF][4], bl[NF][4];
#pragma unroll
            for (int nt2 = 0; nt2 < NF; nt2++) {
                uint32_t bo = SWZ64((n0w + nt2 * 16 + b_row) * 64 + b_ch * 16);
                ldsm_x4(bh[nt2], st + T_BHI + bo);
                ldsm_x4(bl[nt2], st + T_BLO + bo);
            }
#pragma unroll
            for (int mt = 0; mt < 4; mt++) {
                uint32_t ao = SWZ64((m0w + mt * 16 + a_row) * 64 + a_ch * 16);
                uint32_t ah[4], al[4];
                ldsm_x4(ah, st + T_AHI + ao);
                ldsm_x4(al, st + T_ALO + ao);
#pragma unroll
                for (int nt = 0; nt < NT; nt++) {
                    uint32_t h0 = bh[nt >> 1][(nt & 1) * 2], h1 = bh[nt >> 1][(nt & 1) * 2 + 1];
                    uint32_t l0 = bl[nt >> 1][(nt & 1) * 2], l1 = bl[nt >> 1][(nt & 1) * 2 + 1];
                    mma16816(acc[mt][nt], ah, h0, h1);   // hi*hi
                    mma16816(acc[mt][nt], al, h0, h1);   // lo*hi
                    mma16816(acc[mt][nt], ah, l0, l1);   // hi*lo
                }
            }
        }
    }

#pragma unroll
    for (int mt = 0; mt < 4; mt++) {
        int r0 = row0 + m0w + mt * 16 + (lane >> 2);
#pragma unroll
        for (int nt = 0; nt < NT; nt++) {
            int cc = col0 + n0w + nt * 8 + (lane & 3) * 2;
            *reinterpret_cast<float2*>(&C[(size_t)r0 * ldc + cc]) =
                make_float2(acc[mt][nt][0], acc[mt][nt][1]);
            *reinterpret_cast<float2*>(&C[(size_t)(r0 + 8) * ldc + cc]) =
                make_float2(acc[mt][nt][2], acc[mt][nt][3]);
        }
    }
}

// ---------------- K3: GRU gates (register-resident, float4, fast gates) ----------------
__global__ __launch_bounds__(256) void gru_kernel(
    const float* __restrict__ bgru, const float* __restrict__ ggru,
    const float* __restrict__ betag, float* __restrict__ out, int t)
{
    __shared__ float red[64];
    int b = blockIdx.x, tid = threadIdx.x;
    const float4* row4 = reinterpret_cast<const float4*>(g_parts + (size_t)b * 3072);
    const float4* bg4  = reinterpret_cast<const float4*>(bgru);

    float4 loc[3];
    float s = 0.f, ss = 0.f;
#pragma unroll
    for (int jj = 0; jj < 3; jj++) {
        float4 x = row4[tid + jj * 256];
        float4 bb = bg4[tid + jj * 256];
        x.x += bb.x; x.y += bb.y; x.z += bb.z; x.w += bb.w;
        loc[jj] = x;
        s += x.x + x.y + x.z + x.w;
        ss += x.x * x.x + x.y * x.y + x.z * x.z + x.w * x.w;
    }
    blockReduce2(s, ss, red);
    float mean = s * (1.f / 3072.f);
    float rstd = rsqrtf(ss * (1.f / 3072.f) - mean * mean + LN_EPS);

    const float4* gg4 = reinterpret_cast<const float4*>(ggru);
    const float4* bt4 = reinterpret_cast<const float4*>(betag);
    float V[3][4];
#pragma unroll
    for (int jj = 0; jj < 3; jj++) {
        float4 g = gg4[tid + jj * 256];
        float4 be = bt4[tid + jj * 256];
        V[jj][0] = (loc[jj].x - mean) * rstd * g.x + be.x;
        V[jj][1] = (loc[jj].y - mean) * rstd * g.y + be.y;
        V[jj][2] = (loc[jj].z - mean) * rstd * g.z + be.z;
        V[jj][3] = (loc[jj].w - mean) * rstd * g.w + be.w;
    }

    float4 dp = *reinterpret_cast<const float4*>(&g_deter[(size_t)b * 1024 + tid * 4]);
    float dpv[4] = {dp.x, dp.y, dp.z, dp.w};
    float dn[4];
#pragma unroll
    for (int q = 0; q < 4; q++) {
        float reset  = fsig(V[0][q]);
        float cand   = ftanh(reset * V[1][q]);
        float update = fsig(V[2][q] - 1.f);
        dn[q] = update * cand + (1.f - update) * dpv[q];
    }
    *reinterpret_cast<float4*>(&g_deter[(size_t)b * 1024 + tid * 4]) =
        make_float4(dn[0], dn[1], dn[2], dn[3]);
    *reinterpret_cast<float4*>(&out[(size_t)b * (TT * OUTW) + (size_t)t * OUTW + 128 + tid * 4]) =
        make_float4(dn[0], dn[1], dn[2], dn[3]);
    size_t o = (size_t)b * 2048 + 1024 + tid * 4;
    split_store4(dn, &g_ahi[o], &g_alo[o]);
}

// ---------------- K6: fused e1-LN/ELU + e2 GEMM (64-k tiles) + stats + img(t+1) ----------------
// 256 blocks x 256 threads, 8 rows each. Dynamic smem 32KB aliased:
// e2 phase uses it as ws[64][128] (32KB exactly); img phase as vals[8][1024].
__global__ __launch_bounds__(256) void e2img_kernel(
    const float* __restrict__ be1, const float* __restrict__ ge1,
    const float* __restrict__ betae1,
    const float* __restrict__ W, const float* __restrict__ bias,
    const float* __restrict__ action, const float* __restrict__ Wimg,
    const float* __restrict__ bimg, const float* __restrict__ gimg,
    const float* __restrict__ betaimg,
    float* __restrict__ out, int t, int do_img)
{
    extern __shared__ float dsm[];           // 32KB: ws[64][128] (e2) / vals[8][1024] (img)
    __shared__ float hs[8][68];
    __shared__ float xin[8][72];             // stoch cols 0..63 filled by e2 epilogue
    __shared__ float red[64];
    __shared__ float smean[8], srstd[8];
    int tid = threadIdx.x;
    int r0 = blockIdx.x * 8;
    int w = tid >> 5, lane = tid & 31;

    // pre-stage img action inputs (independent of phases 1-3)
    if (do_img) {
        for (int e = tid; e < 8 * ACT; e += 256) {
            int r = e / ACT, c = e % ACT;
            xin[r][STOCH + c] = action[(size_t)(r0 + r) * (TT * ACT) + (t + 1) * ACT + c];
        }
    }

    // phase 1: warp-per-row LN stats of e1raw
    {
        const float4* row4 = reinterpret_cast<const float4*>(g_e1raw + (size_t)(r0 + w) * 1024);
        const float4* b4 = reinterpret_cast<const float4*>(be1);
        float s = 0.f, ss = 0.f;
#pragma unroll
        for (int i = 0; i < 8; i++) {
            float4 x = row4[lane + i * 32];
            float4 bb = b4[lane + i * 32];
            x.x += bb.x; x.y += bb.y; x.z += bb.z; x.w += bb.w;
            s += x.x + x.y + x.z + x.w;
            ss += x.x * x.x + x.y * x.y + x.z * x.z + x.w * x.w;
        }
#pragma unroll
        for (int o = 16; o > 0; o >>= 1) {
            s  += __shfl_down_sync(0xffffffffu, s, o);
            ss += __shfl_down_sync(0xffffffffu, ss, o);
        }
        if (lane == 0) {
            float mean = s * (1.f / 1024.f);
            smean[w] = mean;
            srstd[w] = rsqrtf(ss * (1.f / 1024.f) - mean * mean + LN_EPS);
        }
    }
    __syncthreads();

    // phase 2: e2 GEMM with on-the-fly LN+ELU, 64-wide K tiles (half the syncs)
    int col = tid & 127, rl = tid >> 7;
    float acc[4];
#pragma unroll
    for (int q = 0; q < 4; q++) acc[q] = 0.f;

    for (int k0 = 0; k0 < 1024; k0 += 64) {
        if (tid < 128) {
            int rr = tid >> 4, k4 = (tid & 15) * 4;
            int c = k0 + k4;
            float4 v = *reinterpret_cast<const float4*>(&g_e1raw[(size_t)(r0 + rr) * 1024 + c]);
            float4 bb = *reinterpret_cast<const float4*>(&be1[c]);
            float4 g  = *reinterpret_cast<const float4*>(&ge1[c]);
            float4 be = *reinterpret_cast<const float4*>(&betae1[c]);
            float mean = smean[rr], rstd = srstd[rr];
            hs[rr][k4]     = elu1(((v.x + bb.x) - mean) * rstd * g.x + be.x);
            hs[rr][k4 + 1] = elu1(((v.y + bb.y) - mean) * rstd * g.y + be.y);
            hs[rr][k4 + 2] = elu1(((v.z + bb.z) - mean) * rstd * g.z + be.z);
            hs[rr][k4 + 3] = elu1(((v.w + bb.w) - mean) * rstd * g.w + be.w);
        }
#pragma unroll
        for (int i = 0; i < 8; i++) {
            int idx = tid + i * 256;
            int kk = idx >> 5, c4 = (idx & 31) * 4;
            float4 v = *reinterpret_cast<const float4*>(&W[(size_t)(k0 + kk) * 128 + c4]);
            dsm[kk * 128 + c4]     = v.x;
            dsm[kk * 128 + c4 + 1] = v.y;
            dsm[kk * 128 + c4 + 2] = v.z;
            dsm[kk * 128 + c4 + 3] = v.w;
        }
        __syncthreads();
#pragma unroll
        for (int kk = 0; kk < 64; kk++) {
            float wv = dsm[kk * 128 + col];
#pragma unroll
            for (int q = 0; q < 4; q++)
                acc[q] = fmaf(hs[rl + 2 * q][kk], wv, acc[q]);
        }
        __syncthreads();
    }

    // phase 3: stats epilogue; stoch -> xin for img
    float bv = bias[col];
#pragma unroll
    for (int q = 0; q < 4; q++) {
        int r = r0 + rl + 2 * q;
        float sv = acc[q] + bv;
        if (col < 64) {
            xin[rl + 2 * q][col] = sv;
            out[(size_t)r * (TT * OUTW) + (size_t)t * OUTW + col] = sv;
        } else {
            float sp = fmaxf(sv, 0.f) + __logf(1.f + __expf(-fabsf(sv)));
            out[(size_t)r * (TT * OUTW) + (size_t)t * OUTW + col] = sp + 0.1f;
        }
    }

    // phase 4: img(t+1) for the same 8 rows (actions already staged)
    if (do_img) {
        __syncthreads();
        img_body(xin, dsm, red, Wimg, bimg, gimg, betaimg, r0);
    }
}

// ---------------- launcher ----------------
#define MMA_SMEM_32 98304    // 3 x (16384 + 2*8192)
#define MMA_SMEM_16 73728    // 3 x (16384 + 2*4096)
#define IMG_DSM     32768

extern "C" void kernel_launch(void* const* d_in, const int* in_sizes, int n_in,
                              void* d_out, int out_size)
{
    const float* action   = (const float*)d_in[0];
    const float* W_img    = (const float*)d_in[1];
    const float* b_img    = (const float*)d_in[2];
    const float* g_img    = (const float*)d_in[3];
    const float* beta_img = (const float*)d_in[4];
    const float* W_gru    = (const float*)d_in[5];
    const float* b_gru    = (const float*)d_in[6];
    const float* g_gru    = (const float*)d_in[7];
    const float* beta_gru = (const float*)d_in[8];
    const float* W_e1     = (const float*)d_in[9];    // [5,1024,1024] -> slice 0
    const float* b_e1     = (const float*)d_in[10];
    const float* g_e1     = (const float*)d_in[11];
    const float* beta_e1  = (const float*)d_in[12];
    const float* W_e2     = (const float*)d_in[13];   // [5,1024,128] -> slice 0
    const float* b_e2     = (const float*)d_in[14];
    float* out = (float*)d_out;

    cudaFuncSetAttribute(mma_gemm_t<32>, cudaFuncAttributeMaxDynamicSharedMemorySize, MMA_SMEM_32);
    cudaFuncSetAttribute(mma_gemm_t<16>, cudaFuncAttributeMaxDynamicSharedMemorySize, MMA_SMEM_16);

    init_kernel<<<(BATCH * DETER + 255) / 256, 256>>>();

    __nv_bfloat16 *wgh, *wgl, *weh, *wel;
    cudaGetSymbolAddress((void**)&wgh, g_wgru_hi);
    cudaGetSymbolAddress((void**)&wgl, g_wgru_lo);
    cudaGetSymbolAddress((void**)&weh, g_we1_hi);
    cudaGetSymbolAddress((void**)&wel, g_we1_lo);
    wprep_kernel<<<dim3(3072 / 32, 2048 / 32), 256>>>(W_gru, wgh, wgl, 2048, 3072);
    wprep_kernel<<<dim3(1024 / 32, 1024 / 32), 256>>>(W_e1, weh, wel, 1024, 1024);

    // t=0 img (stoch = 0)
    img_kernel<<<BATCH / 8, 256, IMG_DSM>>>(action, W_img, b_img, g_img, beta_img, 0);

    for (int t = 0; t < TT; t++) {
        mma_gemm_t<32><<<dim3(3072 / 128, BATCH / 128), 256, MMA_SMEM_32>>>(0);
        gru_kernel<<<BATCH, 256>>>(b_gru, g_gru, beta_gru, out, t);
        mma_gemm_t<16><<<dim3(1024 / 64, BATCH / 128), 256, MMA_SMEM_16>>>(1);
        e2img_kernel<<<BATCH / 8, 256, IMG_DSM>>>(
            b_e1, g_e1, beta_e1, W_e2, b_e2,
            action, W_img, b_img, g_img, beta_img,
            out, t, (t + 1 < TT) ? 1 : 0);
    }
}